// round 11
// baseline (speedup 1.0000x reference)
#include <cuda_runtime.h>
#include <cuda_fp16.h>
#include <cstdint>

#define BSZ 2
#define SEQ 2048
#define DIM 1024
#define NHEAD 16
#define HDIM 64
#define MROWS (BSZ * SEQ)   // 4096

// Scratch (allocation-free requirement -> __device__ globals), all fp16.
__device__ __half g_hin[(size_t)3 * MROWS * DIM];  // converted inputs Q,K,V
__device__ __half g_hwt[(size_t)4 * DIM * DIM];    // W^T fp16 (Wq pre-scaled)
__device__ __half g_hq[(size_t)MROWS * DIM];       // q proj (scaled)
__device__ __half g_hk[(size_t)MROWS * DIM];       // k proj
__device__ __half g_vt[(size_t)BSZ * DIM * SEQ];   // v proj, transposed [b][dim][s]
__device__ __half g_hctx[(size_t)MROWS * DIM];     // attention output
__device__ uint32_t g_mb[(size_t)SEQ * (SEQ / 32)]; // mask bit-packed, 64 w/row

// 0.125 (1/sqrt(64)) * log2(e): folded into Wq/bq so softmax can use exp2.
#define QSCALE 0.1803368801111137f

__device__ __forceinline__ uint32_t smem_u32(const void* p) {
    uint32_t a;
    asm("{ .reg .u64 t; cvta.to.shared.u64 t, %1; cvt.u32.u64 %0, t; }"
        : "=r"(a) : "l"(p));
    return a;
}

__device__ __forceinline__ void cp_async16(uint32_t dst, const void* src) {
    asm volatile("cp.async.cg.shared.global [%0], [%1], 16;"
                 :: "r"(dst), "l"(src));
}
#define CP_COMMIT() asm volatile("cp.async.commit_group;" ::: "memory")
#define CP_WAIT0()  asm volatile("cp.async.wait_group 0;" ::: "memory")
#define CP_WAIT1()  asm volatile("cp.async.wait_group 1;" ::: "memory")

__device__ __forceinline__ uint32_t pack_h2(float lo, float hi) {
    __half2 h = __floats2half2_rn(lo, hi);
    return *(uint32_t*)&h;
}

__device__ __forceinline__ float ex2(float x) {
    float r;
    asm("ex2.approx.ftz.f32 %0, %1;" : "=f"(r) : "f"(x));
    return r;
}

// ldmatrix x4: loads four 8x8 b16 tiles.
__device__ __forceinline__ void ldsm_x4(uint32_t& r0, uint32_t& r1,
                                        uint32_t& r2, uint32_t& r3,
                                        uint32_t addr) {
    asm volatile("ldmatrix.sync.aligned.m8n8.x4.shared.b16 "
                 "{%0,%1,%2,%3}, [%4];"
                 : "=r"(r0), "=r"(r1), "=r"(r2), "=r"(r3) : "r"(addr));
}

// m16n8k16 fp16 HMMA, fp32 accumulate.
__device__ __forceinline__ void mma_f16(float c[4],
                                        uint32_t a0, uint32_t a1,
                                        uint32_t a2, uint32_t a3,
                                        uint32_t b0, uint32_t b1) {
    asm volatile(
        "mma.sync.aligned.m16n8k16.row.col.f32.f16.f16.f32 "
        "{%0,%1,%2,%3}, {%4,%5,%6,%7}, {%8,%9}, {%0,%1,%2,%3};"
        : "+f"(c[0]), "+f"(c[1]), "+f"(c[2]), "+f"(c[3])
        : "r"(a0), "r"(a1), "r"(a2), "r"(a3), "r"(b0), "r"(b1));
}

// ---------------------------------------------------------------------------
// Input convert: fp32 -> fp16, Q/K/V in one launch (grid.y = 3).
// ---------------------------------------------------------------------------
__global__ __launch_bounds__(256) void convert_in_kernel(
    const float* __restrict__ Q, const float* __restrict__ K,
    const float* __restrict__ V)
{
    const int z = blockIdx.y;
    const float* src = (z == 0) ? Q : (z == 1) ? K : V;
    size_t off = ((size_t)blockIdx.x * 256 + threadIdx.x) * 8;
    float4 v0 = *(const float4*)(src + off);
    float4 v1 = *(const float4*)(src + off + 4);
    __half2* dst = (__half2*)(g_hin + (size_t)z * MROWS * DIM + off);
    uint4 pk;
    pk.x = pack_h2(v0.x, v0.y);
    pk.y = pack_h2(v0.z, v0.w);
    pk.z = pack_h2(v1.x, v1.y);
    pk.w = pack_h2(v1.z, v1.w);
    *(uint4*)dst = pk;
}

// ---------------------------------------------------------------------------
// Mask pack: g_mb[q][k/32] bit k%32 = (mask[q][k] != 0).
// ---------------------------------------------------------------------------
__global__ __launch_bounds__(256) void pack_mask_kernel(
    const int* __restrict__ mask)
{
    int idx = blockIdx.x * 256 + threadIdx.x;   // word index
    const int* src = mask + (size_t)idx * 32;
    uint32_t bits = 0;
#pragma unroll
    for (int u = 0; u < 8; ++u) {
        int4 v = *(const int4*)(src + u * 4);
        bits |= (v.x ? 1u : 0u) << (u * 4);
        bits |= (v.y ? 1u : 0u) << (u * 4 + 1);
        bits |= (v.z ? 1u : 0u) << (u * 4 + 2);
        bits |= (v.w ? 1u : 0u) << (u * 4 + 3);
    }
    g_mb[idx] = bits;
}

// ---------------------------------------------------------------------------
// Weight transpose+convert: g_hwt[z][n][k] = fp16(W[z][k][n] * scale).
// ---------------------------------------------------------------------------
__global__ __launch_bounds__(256) void convert_wt_kernel(
    const float* __restrict__ Wq, const float* __restrict__ Wk,
    const float* __restrict__ Wv, const float* __restrict__ Wo)
{
    __shared__ float t[32][33];
    const int z = blockIdx.z;
    const float* W = (z == 0) ? Wq : (z == 1) ? Wk : (z == 2) ? Wv : Wo;
    const float scale = (z == 0) ? QSCALE : 1.0f;
    __half* WT = g_hwt + (size_t)z * DIM * DIM;
    const int bx = blockIdx.x * 32;   // n
    const int by = blockIdx.y * 32;   // k
    const int x = threadIdx.x, y = threadIdx.y;
#pragma unroll
    for (int j = 0; j < 32; j += 8)
        t[y + j][x] = W[(size_t)(by + y + j) * DIM + bx + x];
    __syncthreads();
#pragma unroll
    for (int j = 0; j < 32; j += 8)
        WT[(size_t)(bx + y + j) * DIM + by + x] =
            __float2half(t[x][y + j] * scale);
}

// ---------------------------------------------------------------------------
// fp16 GEMM (unchanged R10): 128x128 tile, BK=32, cp.async 3-stage, ldmatrix.
// MODE 0: half row-major out.  MODE 1: half transposed out ([b][dim][s]).
// MODE 2: float row-major out.
// ---------------------------------------------------------------------------
#define PAH 40                               // halves pitch => 80 B
#define SB_OFF (128 * PAH * 2)               // 10240 B: B within stage
#define STAGE_BYTES (2 * 128 * PAH * 2)      // 20480 B
#define OFF_BIAS_B (3 * STAGE_BYTES)         // 61440
#define GEMM_SMEM_BYTES (OFF_BIAS_B + 128 * 4)

__device__ __forceinline__ void gemm_issue_h(
    uint32_t sbase, int s, int ch, const __half* __restrict__ A,
    const __half* __restrict__ WT, int m0, int n0, int tid)
{
    uint32_t sa = sbase + (uint32_t)(s * STAGE_BYTES);
    uint32_t sb = sa + SB_OFF;
    const __half* Ap = A + (size_t)m0 * DIM + ch * 32;
    const __half* Wp = WT + (size_t)n0 * DIM + ch * 32;
#pragma unroll
    for (int u = 0; u < 2; ++u) {
        int i = tid + u * 256;               // 512: 128 rows x 4 chunks
        int row = i >> 2, c16 = i & 3;
        cp_async16(sa + (uint32_t)(row * 80 + c16 * 16),
                   Ap + (size_t)row * DIM + c16 * 8);
        cp_async16(sb + (uint32_t)(row * 80 + c16 * 16),
                   Wp + (size_t)row * DIM + c16 * 8);
    }
}

template <int MODE>
__device__ __forceinline__ void gemm_body_h(
    const __half* __restrict__ A, const __half* __restrict__ WT,
    const float* __restrict__ bias, void* Cout, float bscale, char* smc)
{
    float* sbias = (float*)(smc + OFF_BIAS_B);
    const uint32_t sbase = smem_u32(smc);
    const int tid = threadIdx.x;
    const int wid = tid >> 5, lane = tid & 31;
    const int wm = wid >> 2, wn = wid & 3;
    const int g = lane >> 2, tig = lane & 3;
    const int n0 = blockIdx.x * 128;
    const int m0 = blockIdx.y * 128;

    if (tid < 128) sbias[tid] = bias[n0 + tid] * bscale;

    const uint32_t afoff = (uint32_t)(
        (wm * 64 + ((lane >> 3) & 1) * 8 + (lane & 7)) * 80 +
        ((lane >> 4) & 1) * 16);
    const uint32_t bfoff = (uint32_t)(
        (wn * 32 + ((lane >> 4) & 1) * 8 + (lane & 7)) * 80 +
        ((lane >> 3) & 1) * 16);

    float c[4][4][4];
#pragma unroll
    for (int mt = 0; mt < 4; ++mt)
#pragma unroll
        for (int nt = 0; nt < 4; ++nt)
#pragma unroll
            for (int q = 0; q < 4; ++q) c[mt][nt][q] = 0.f;

    gemm_issue_h(sbase, 0, 0, A, WT, m0, n0, tid);
    CP_COMMIT();
    gemm_issue_h(sbase, 1, 1, A, WT, m0, n0, tid);
    CP_COMMIT();

    for (int ch = 0; ch < 32; ++ch) {
        if (ch == 31) CP_WAIT0(); else CP_WAIT1();
        __syncthreads();
        if (ch < 30) {
            gemm_issue_h(sbase, (ch + 2) % 3, ch + 2, A, WT, m0, n0, tid);
            CP_COMMIT();
        }

        const uint32_t sAb = sbase + (uint32_t)((ch % 3) * STAGE_BYTES);
        const uint32_t sBb = sAb + SB_OFF;

#pragma unroll
        for (int kk = 0; kk < 2; ++kk) {
            uint32_t af[4][4], bf[4][2];
#pragma unroll
            for (int mt = 0; mt < 4; ++mt)
                ldsm_x4(af[mt][0], af[mt][1], af[mt][2], af[mt][3],
                        sAb + afoff + mt * 1280 + kk * 32);
#pragma unroll
            for (int p = 0; p < 2; ++p)
                ldsm_x4(bf[2 * p][0], bf[2 * p][1],
                        bf[2 * p + 1][0], bf[2 * p + 1][1],
                        sBb + bfoff + p * 1280 + kk * 32);
#pragma unroll
            for (int mt = 0; mt < 4; ++mt)
#pragma unroll
                for (int nt = 0; nt < 4; ++nt)
                    mma_f16(c[mt][nt], af[mt][0], af[mt][1], af[mt][2],
                            af[mt][3], bf[nt][0], bf[nt][1]);
        }
    }

#pragma unroll
    for (int mt = 0; mt < 4; ++mt) {
        int row = m0 + wm * 64 + mt * 16 + g;
#pragma unroll
        for (int nt = 0; nt < 4; ++nt) {
            int col = n0 + wn * 32 + nt * 8 + 2 * tig;
            float b0 = sbias[col - n0], b1 = sbias[col - n0 + 1];
            float v00 = c[mt][nt][0] + b0, v01 = c[mt][nt][1] + b1;
            float v10 = c[mt][nt][2] + b0, v11 = c[mt][nt][3] + b1;
            if (MODE == 0) {
                __half* C = (__half*)Cout;
                *(uint32_t*)(C + (size_t)row * DIM + col) = pack_h2(v00, v01);
                *(uint32_t*)(C + (size_t)(row + 8) * DIM + col) =
                    pack_h2(v10, v11);
            } else if (MODE == 1) {
                __half* VT = (__half*)Cout;   // [b][dim][s]
                int bb = row >> 11, ss = row & 2047;
                VT[((size_t)bb * DIM + col) * SEQ + ss] = __float2half(v00);
                VT[((size_t)bb * DIM + col + 1) * SEQ + ss] = __float2half(v01);
                VT[((size_t)bb * DIM + col) * SEQ + ss + 8] = __float2half(v10);
                VT[((size_t)bb * DIM + col + 1) * SEQ + ss + 8] =
                    __float2half(v11);
            } else {
                float* C = (float*)Cout;
                *(float2*)(C + (size_t)row * DIM + col) = make_float2(v00, v01);
                *(float2*)(C + (size_t)(row + 8) * DIM + col) =
                    make_float2(v10, v11);
            }
        }
    }
}

__global__ __launch_bounds__(256, 2) void qkv_gemm_kernel(
    const float* __restrict__ bq, const float* __restrict__ bk,
    const float* __restrict__ bv)
{
    extern __shared__ char smc[];
    const int z = blockIdx.z;
    const __half* A = g_hin + (size_t)z * MROWS * DIM;
    const __half* WT = g_hwt + (size_t)z * DIM * DIM;
    if (z == 0)
        gemm_body_h<0>(A, WT, bq, g_hq, QSCALE, smc);
    else if (z == 1)
        gemm_body_h<0>(A, WT, bk, g_hk, 1.0f, smc);
    else
        gemm_body_h<1>(A, WT, bv, g_vt, 1.0f, smc);
}

__global__ __launch_bounds__(256, 2) void oproj_gemm_kernel(
    const float* __restrict__ bias, float* __restrict__ C)
{
    extern __shared__ char smc[];
    gemm_body_h<2>(g_hctx, g_hwt + (size_t)3 * DIM * DIM, bias, C, 1.0f, smc);
}

// ---------------------------------------------------------------------------
// FA2 attention, fp16 MMAs + ldmatrix + bit-packed mask, M=32 per warp.
// Block = 128 threads (4 warps) x 128 q rows; warp owns 32 q rows (2 m-tiles).
// K/V fragments loaded once per warp, reused by both m-tiles -> ~45% less LDS.
// ---------------------------------------------------------------------------
#define APH 72                                // halves pitch => 144 B
#define Q_BYTES (128 * APH * 2)               // 18432
#define KV_V_OFF (64 * APH * 2)               // 9216
#define KV_STAGE_B (2 * 64 * APH * 2)         // 18432
#define ATTN_SMEM_BYTES (Q_BYTES + 2 * KV_STAGE_B)   // 55296

__global__ __launch_bounds__(128, 3) void attn_mma_kernel()
{
    extern __shared__ char smc[];
    const uint32_t sbase = smem_u32(smc);

    const int tid = threadIdx.x;
    const int wid = tid >> 5, lane = tid & 31;
    const int g = lane >> 2, tig = lane & 3;
    const int q0 = blockIdx.x * 128;
    const int h = blockIdx.y;
    const int b = blockIdx.z;

    const __half* qb = g_hq + ((size_t)b * SEQ + q0) * DIM + h * HDIM;
    const __half* kb = g_hk + (size_t)b * SEQ * DIM + h * HDIM;
    const __half* vtb = g_vt + ((size_t)b * DIM + h * HDIM) * SEQ;

    // ldmatrix per-lane address offsets (warp owns rows wid*32..wid*32+31).
    const uint32_t qoff = (uint32_t)(
        (wid * 32 + ((lane >> 3) & 1) * 8 + (lane & 7)) * 144 +
        ((lane >> 4) & 1) * 16);
    const uint32_t bfoff = (uint32_t)(
        (((lane >> 4) & 1) * 8 + (lane & 7)) * 144 +
        ((lane >> 3) & 1) * 16);

    // Prologue: stage Q (128x64) + K/V tile 0 (128 threads).
#pragma unroll
    for (int u = 0; u < 8; ++u) {
        int i = tid + u * 128;               // 1024: 128 rows x 8 chunks
        int row = i >> 3, c16 = i & 7;
        cp_async16(sbase + (uint32_t)(row * 144 + c16 * 16),
                   qb + (size_t)row * DIM + c16 * 8);
    }
    {
        uint32_t kst = sbase + Q_BYTES;
        uint32_t vst = kst + KV_V_OFF;
#pragma unroll
        for (int u = 0; u < 4; ++u) {
            int i = tid + u * 128;           // 512: 64 rows x 8 chunks
            int row = i >> 3, c16 = i & 7;
            cp_async16(kst + (uint32_t)(row * 144 + c16 * 16),
                       kb + (size_t)row * DIM + c16 * 8);
            cp_async16(vst + (uint32_t)(row * 144 + c16 * 16),
                       vtb + (size_t)row * SEQ + c16 * 8);
        }
    }
    CP_COMMIT();

    float mr[2][2] = {{-1e30f, -1e30f}, {-1e30f, -1e30f}};
    float lr[2][2] = {{0.f, 0.f}, {0.f, 0.f}};
    float o[2][8][4];
#pragma unroll
    for (int mt = 0; mt < 2; ++mt)
#pragma unroll
        for (int nt = 0; nt < 8; ++nt)
#pragma unroll
            for (int q = 0; q < 4; ++q) o[mt][nt][q] = 0.f;

    // Bit-packed mask rows: this thread covers q rows wid*32+g +{0,8,16,24}.
    const uint32_t* bmr = g_mb + (size_t)(q0 + wid * 32 + g) * (SEQ / 32);

    for (int kt = 0; kt < SEQ / 64; ++kt) {
        const int kg0 = kt * 64;

        // Mask bits for this tile (hoisted; L2-resident).
        uint2 w[2][2];
        w[0][0] = *(const uint2*)(bmr + (kg0 >> 5));
        w[0][1] = *(const uint2*)(bmr + 8 * (SEQ / 32) + (kg0 >> 5));
        w[1][0] = *(const uint2*)(bmr + 16 * (SEQ / 32) + (kg0 >> 5));
        w[1][1] = *(const uint2*)(bmr + 24 * (SEQ / 32) + (kg0 >> 5));

        CP_WAIT0();
        __syncthreads();

        // Prefetch next K/V tile.
        if (kt < SEQ / 64 - 1) {
            int s = (kt + 1) & 1;
            int kg = (kt + 1) * 64;
            uint32_t kst = sbase + Q_BYTES + (uint32_t)(s * KV_STAGE_B);
            uint32_t vst = kst + KV_V_OFF;
#pragma unroll
            for (int u = 0; u < 4; ++u) {
                int i = tid + u * 128;
                int row = i >> 3, c16 = i & 7;
                cp_async16(kst + (uint32_t)(row * 144 + c16 * 16),
                           kb + (size_t)(kg + row) * DIM + c16 * 8);
                cp_async16(vst + (uint32_t)(row * 144 + c16 * 16),
                           vtb + (size_t)row * SEQ + kg + c16 * 8);
            }
            CP_COMMIT();
        }

        const uint32_t kbase_s = sbase + Q_BYTES
                                 + (uint32_t)((kt & 1) * KV_STAGE_B);
        const uint32_t vbase_s = kbase_s + KV_V_OFF;

        // S = Q @ K^T : 4 k16 steps, 2 m-tiles x 8 n-tiles.
        float c[2][8][4];
#pragma unroll
        for (int mt = 0; mt < 2; ++mt)
#pragma unroll
            for (int nt = 0; nt < 8; ++nt)
#pragma unroll
                for (int q = 0; q < 4; ++q) c[mt][nt][q] = 0.f;

#pragma unroll
        for (int kk = 0; kk < 4; ++kk) {
            uint32_t a0[4], a1[4];
            ldsm_x4(a0[0], a0[1], a0[2], a0[3], sbase + qoff + kk * 32);
            ldsm_x4(a1[0], a1[1], a1[2], a1[3],
                    sbase + qoff + 2304 + kk * 32);
#pragma unroll
            for (int p = 0; p < 4; ++p) {
                uint32_t b0, b1, b2, b3;
                ldsm_x4(b0, b1, b2, b3,
                        kbase_s + bfoff + p * 2304 + kk * 32);
                mma_f16(c[0][2 * p], a0[0], a0[1], a0[2], a0[3], b0, b1);
                mma_f16(c[0][2 * p + 1], a0[0], a0[1], a0[2], a0[3], b2, b3);
                mma_f16(c[1][2 * p], a1[0], a1[1], a1[2], a1[3], b0, b1);
                mma_f16(c[1][2 * p + 1], a1[0], a1[1], a1[2], a1[3], b2, b3);
            }
        }

        // Per m-tile: mask, online softmax (log2 units), rescale O.
#pragma unroll
        for (int mt = 0; mt < 2; ++mt) {
            float mx0 = -1e30f, mx1 = -1e30f;
#pragma unroll
            for (int nt = 0; nt < 8; ++nt) {
                uint32_t wa = (nt < 4) ? w[mt][0].x : w[mt][0].y;
                uint32_t wb = (nt < 4) ? w[mt][1].x : w[mt][1].y;
                int sh = (nt & 3) * 8 + 2 * tig;
                uint32_t ta = wa >> sh, tb = wb >> sh;
                c[mt][nt][0] = (ta & 1u) ? c[mt][nt][0] : -1e30f;
                c[mt][nt][1] = (ta & 2u) ? c[mt][nt][1] : -1e30f;
                c[mt][nt][2] = (tb & 1u) ? c[mt][nt][2] : -1e30f;
                c[mt][nt][3] = (tb & 2u) ? c[mt][nt][3] : -1e30f;
                mx0 = fmaxf(mx0, fmaxf(c[mt][nt][0], c[mt][nt][1]));
                mx1 = fmaxf(mx1, fmaxf(c[mt][nt][2], c[mt][nt][3]));
            }
            mx0 = fmaxf(mx0, __shfl_xor_sync(0xffffffffu, mx0, 1));
            mx0 = fmaxf(mx0, __shfl_xor_sync(0xffffffffu, mx0, 2));
            mx1 = fmaxf(mx1, __shfl_xor_sync(0xffffffffu, mx1, 1));
            mx1 = fmaxf(mx1, __shfl_xor_sync(0xffffffffu, mx1, 2));

            float mn0 = fmaxf(mr[mt][0], mx0), mn1 = fmaxf(mr[mt][1], mx1);
            float al0 = ex2(mr[mt][0] - mn0), al1 = ex2(mr[mt][1] - mn1);
            float s0 = 0.f, s1 = 0.f;
#pragma unroll
            for (int nt = 0; nt < 8; ++nt) {
                float p0 = ex2(c[mt][nt][0] - mn0);
                float p1 = ex2(c[mt][nt][1] - mn0);
                float p2 = ex2(c[mt][nt][2] - mn1);
                float p3 = ex2(c[mt][nt][3] - mn1);
                s0 += p0 + p1;
                s1 += p2 + p3;
                c[mt][nt][0] = p0; c[mt][nt][1] = p1;
                c[mt][nt][2] = p2; c[mt][nt][3] = p3;
            }
            s0 += __shfl_xor_sync(0xffffffffu, s0, 1);
            s0 += __shfl_xor_sync(0xffffffffu, s0, 2);
            s1 += __shfl_xor_sync(0xffffffffu, s1, 1);
            s1 += __shfl_xor_sync(0xffffffffu, s1, 2);
            lr[mt][0] = lr[mt][0] * al0 + s0;
            lr[mt][1] = lr[mt][1] * al1 + s1;
            mr[mt][0] = mn0; mr[mt][1] = mn1;
#pragma unroll
            for (int nt = 0; nt < 8; ++nt) {
                o[mt][nt][0] *= al0; o[mt][nt][1] *= al0;
                o[mt][nt][2] *= al1; o[mt][nt][3] *= al1;
            }
        }

        // O += P @ V: A-frags straight from S C-frags; V B-frags shared
        // across both m-tiles.
#pragma unroll
        for (int kk = 0; kk < 4; ++kk) {
            uint32_t pa[2][4];
#pragma unroll
            for (int mt = 0; mt < 2; ++mt) {
                pa[mt][0] = pack_h2(c[mt][2 * kk][0], c[mt][2 * kk][1]);
                pa[mt][1] = pack_h2(c[mt][2 * kk][2], c[mt][2 * kk][3]);
                pa[mt][2] = pack_h2(c[mt][2 * kk + 1][0], c[mt][2 * kk + 1][1]);
                pa[mt][3] = pack_h2(c[mt][2 * kk + 1][2], c[mt][2 * kk + 1][3]);
            }
#pragma unroll
            for (int p = 0; p < 4; ++p) {
                uint32_t b0, b1, b2, b3;
                ldsm_x4(b0, b1, b2, b3,
                        vbase_s + bfoff + p * 2304 + kk * 32);
                mma_f16(o[0][2 * p], pa[0][0], pa[0][1], pa[0][2], pa[0][3],
                        b0, b1);
                mma_f16(o[0][2 * p + 1], pa[0][0], pa[0][1], pa[0][2],
                        pa[0][3], b2, b3);
                mma_f16(o[1][2 * p], pa[1][0], pa[1][1], pa[1][2], pa[1][3],
                        b0, b1);
                mma_f16(o[1][2 * p + 1], pa[1][0], pa[1][1], pa[1][2],
                        pa[1][3], b2, b3);
            }
        }
    }

    // Final normalize + store fp16 (merged-head layout).
#pragma unroll
    for (int mt = 0; mt < 2; ++mt) {
        float inv0 = 1.f / lr[mt][0], inv1 = 1.f / lr[mt][1];
        __half* od = g_hctx
            + ((size_t)b * SEQ + q0 + wid * 32 + mt * 16 + g) * DIM + h * HDIM;
#pragma unroll
        for (int nt = 0; nt < 8; ++nt) {
            *(uint32_t*)(od + nt * 8 + 2 * tig) =
                pack_h2(o[mt][nt][0] * inv0, o[mt][nt][1] * inv0);
            *(uint32_t*)(od + (size_t)8 * DIM + nt * 8 + 2 * tig) =
                pack_h2(o[mt][nt][2] * inv1, o[mt][nt][3] * inv1);
        }
    }
}

// ---------------------------------------------------------------------------
// Launch
// ---------------------------------------------------------------------------
extern "C" void kernel_launch(void* const* d_in, const int* in_sizes, int n_in,
                              void* d_out, int out_size)
{
    (void)in_sizes; (void)n_in; (void)out_size;
    const float* Q  = (const float*)d_in[0];
    const float* K  = (const float*)d_in[1];
    const float* V  = (const float*)d_in[2];
    const int* mask = (const int*)d_in[3];
    const float* Wq = (const float*)d_in[4];
    const float* bq = (const float*)d_in[5];
    const float* Wk = (const float*)d_in[6];
    const float* bk = (const float*)d_in[7];
    const float* Wv = (const float*)d_in[8];
    const float* bv = (const float*)d_in[9];
    const float* Wo = (const float*)d_in[10];
    const float* bo = (const float*)d_in[11];
    float* out = (float*)d_out;

    cudaFuncSetAttribute(qkv_gemm_kernel,
                         cudaFuncAttributeMaxDynamicSharedMemorySize,
                         GEMM_SMEM_BYTES);
    cudaFuncSetAttribute(oproj_gemm_kernel,
                         cudaFuncAttributeMaxDynamicSharedMemorySize,
                         GEMM_SMEM_BYTES);
    cudaFuncSetAttribute(attn_mma_kernel,
                         cudaFuncAttributeMaxDynamicSharedMemorySize,
                         ATTN_SMEM_BYTES);

    // Convert inputs and weights to fp16; pack the mask to bits.
    dim3 cigrid(MROWS * DIM / (256 * 8), 3);
    convert_in_kernel<<<cigrid, 256>>>(Q, K, V);
    pack_mask_kernel<<<SEQ * (SEQ / 32) / 256, 256>>>(mask);
    dim3 cwgrid(32, 32, 4), cwblk(32, 8);
    convert_wt_kernel<<<cwgrid, cwblk>>>(Wq, Wk, Wv, Wo);

    // Batched QKV projections.
    dim3 qkvgrid(DIM / 128, MROWS / 128, 3);
    qkv_gemm_kernel<<<qkvgrid, 256, GEMM_SMEM_BYTES>>>(bq, bk, bv);

    // Attention (128-thread blocks, 4 warps x 32 q rows).
    dim3 agrid(SEQ / 128, NHEAD, BSZ);  // (16, 16, 2)
    attn_mma_kernel<<<agrid, 128, ATTN_SMEM_BYTES>>>();

    // Output projection.
    dim3 ggrid(DIM / 128, MROWS / 128);
    oproj_gemm_kernel<<<ggrid, 256, GEMM_SMEM_BYTES>>>(bo, out);
}

// round 12
// speedup vs baseline: 1.1045x; 1.1045x over previous
#include <cuda_runtime.h>
#include <cuda_fp16.h>
#include <cstdint>

#define BSZ 2
#define SEQ 2048
#define DIM 1024
#define NHEAD 16
#define HDIM 64
#define MROWS (BSZ * SEQ)   // 4096

// Scratch (allocation-free requirement -> __device__ globals), all fp16.
__device__ __half g_hin[(size_t)3 * MROWS * DIM];  // converted inputs Q,K,V
__device__ __half g_hwt[(size_t)4 * DIM * DIM];    // W^T fp16 (Wq pre-scaled)
__device__ __half g_hq[(size_t)MROWS * DIM];       // q proj (scaled)
__device__ __half g_hk[(size_t)MROWS * DIM];       // k proj
__device__ __half g_vt[(size_t)BSZ * DIM * SEQ];   // v proj, transposed [b][dim][s]
__device__ __half g_hctx[(size_t)MROWS * DIM];     // attention output
__device__ uint32_t g_mb[(size_t)SEQ * (SEQ / 32)]; // mask bit-packed, 64 w/row

// 0.125 (1/sqrt(64)) * log2(e): folded into Wq/bq so softmax can use exp2.
#define QSCALE 0.1803368801111137f

__device__ __forceinline__ uint32_t smem_u32(const void* p) {
    uint32_t a;
    asm("{ .reg .u64 t; cvta.to.shared.u64 t, %1; cvt.u32.u64 %0, t; }"
        : "=r"(a) : "l"(p));
    return a;
}

__device__ __forceinline__ void cp_async16(uint32_t dst, const void* src) {
    asm volatile("cp.async.cg.shared.global [%0], [%1], 16;"
                 :: "r"(dst), "l"(src));
}
#define CP_COMMIT() asm volatile("cp.async.commit_group;" ::: "memory")
#define CP_WAIT0()  asm volatile("cp.async.wait_group 0;" ::: "memory")
#define CP_WAIT1()  asm volatile("cp.async.wait_group 1;" ::: "memory")

__device__ __forceinline__ uint32_t pack_h2(float lo, float hi) {
    __half2 h = __floats2half2_rn(lo, hi);
    return *(uint32_t*)&h;
}

__device__ __forceinline__ float ex2(float x) {
    float r;
    asm("ex2.approx.ftz.f32 %0, %1;" : "=f"(r) : "f"(x));
    return r;
}

// ldmatrix x4: loads four 8x8 b16 tiles.
__device__ __forceinline__ void ldsm_x4(uint32_t& r0, uint32_t& r1,
                                        uint32_t& r2, uint32_t& r3,
                                        uint32_t addr) {
    asm volatile("ldmatrix.sync.aligned.m8n8.x4.shared.b16 "
                 "{%0,%1,%2,%3}, [%4];"
                 : "=r"(r0), "=r"(r1), "=r"(r2), "=r"(r3) : "r"(addr));
}

// m16n8k16 fp16 HMMA, fp32 accumulate.
__device__ __forceinline__ void mma_f16(float c[4],
                                        uint32_t a0, uint32_t a1,
                                        uint32_t a2, uint32_t a3,
                                        uint32_t b0, uint32_t b1) {
    asm volatile(
        "mma.sync.aligned.m16n8k16.row.col.f32.f16.f16.f32 "
        "{%0,%1,%2,%3}, {%4,%5,%6,%7}, {%8,%9}, {%0,%1,%2,%3};"
        : "+f"(c[0]), "+f"(c[1]), "+f"(c[2]), "+f"(c[3])
        : "r"(a0), "r"(a1), "r"(a2), "r"(a3), "r"(b0), "r"(b1));
}

// ---------------------------------------------------------------------------
// Input convert: fp32 -> fp16, Q/K/V in one launch (grid.y = 3).
// ---------------------------------------------------------------------------
__global__ __launch_bounds__(256) void convert_in_kernel(
    const float* __restrict__ Q, const float* __restrict__ K,
    const float* __restrict__ V)
{
    const int z = blockIdx.y;
    const float* src = (z == 0) ? Q : (z == 1) ? K : V;
    size_t off = ((size_t)blockIdx.x * 256 + threadIdx.x) * 8;
    float4 v0 = *(const float4*)(src + off);
    float4 v1 = *(const float4*)(src + off + 4);
    __half2* dst = (__half2*)(g_hin + (size_t)z * MROWS * DIM + off);
    uint4 pk;
    pk.x = pack_h2(v0.x, v0.y);
    pk.y = pack_h2(v0.z, v0.w);
    pk.z = pack_h2(v1.x, v1.y);
    pk.w = pack_h2(v1.z, v1.w);
    *(uint4*)dst = pk;
}

// ---------------------------------------------------------------------------
// Mask pack: g_mb[q][k/32] bit k%32 = (mask[q][k] != 0).
// ---------------------------------------------------------------------------
__global__ __launch_bounds__(256) void pack_mask_kernel(
    const int* __restrict__ mask)
{
    int idx = blockIdx.x * 256 + threadIdx.x;   // word index
    const int* src = mask + (size_t)idx * 32;
    uint32_t bits = 0;
#pragma unroll
    for (int u = 0; u < 8; ++u) {
        int4 v = *(const int4*)(src + u * 4);
        bits |= (v.x ? 1u : 0u) << (u * 4);
        bits |= (v.y ? 1u : 0u) << (u * 4 + 1);
        bits |= (v.z ? 1u : 0u) << (u * 4 + 2);
        bits |= (v.w ? 1u : 0u) << (u * 4 + 3);
    }
    g_mb[idx] = bits;
}

// ---------------------------------------------------------------------------
// Weight transpose+convert: g_hwt[z][n][k] = fp16(W[z][k][n] * scale).
// ---------------------------------------------------------------------------
__global__ __launch_bounds__(256) void convert_wt_kernel(
    const float* __restrict__ Wq, const float* __restrict__ Wk,
    const float* __restrict__ Wv, const float* __restrict__ Wo)
{
    __shared__ float t[32][33];
    const int z = blockIdx.z;
    const float* W = (z == 0) ? Wq : (z == 1) ? Wk : (z == 2) ? Wv : Wo;
    const float scale = (z == 0) ? QSCALE : 1.0f;
    __half* WT = g_hwt + (size_t)z * DIM * DIM;
    const int bx = blockIdx.x * 32;   // n
    const int by = blockIdx.y * 32;   // k
    const int x = threadIdx.x, y = threadIdx.y;
#pragma unroll
    for (int j = 0; j < 32; j += 8)
        t[y + j][x] = W[(size_t)(by + y + j) * DIM + bx + x];
    __syncthreads();
#pragma unroll
    for (int j = 0; j < 32; j += 8)
        WT[(size_t)(bx + y + j) * DIM + by + x] =
            __float2half(t[x][y + j] * scale);
}

// ---------------------------------------------------------------------------
// fp16 GEMM: 128x128 tile, BK=64 (4 k16 steps/chunk), cp.async 3-stage,
// one barrier per chunk (16 chunks), ldmatrix fragment loads.
// MODE 0: half row-major out.  MODE 1: half transposed out ([b][dim][s]).
// MODE 2: float row-major out.
// ---------------------------------------------------------------------------
#define GPAH 72                              // halves pitch => 144 B
#define SB_OFF (128 * GPAH * 2)              // 18432 B: B within stage
#define STAGE_BYTES (2 * 128 * GPAH * 2)     // 36864 B
#define OFF_BIAS_B (3 * STAGE_BYTES)         // 110592
#define GEMM_SMEM_BYTES (OFF_BIAS_B + 128 * 4)   // 111104

__device__ __forceinline__ void gemm_issue_h(
    uint32_t sbase, int s, int ch, const __half* __restrict__ A,
    const __half* __restrict__ WT, int m0, int n0, int tid)
{
    uint32_t sa = sbase + (uint32_t)(s * STAGE_BYTES);
    uint32_t sb = sa + SB_OFF;
    const __half* Ap = A + (size_t)m0 * DIM + ch * 64;
    const __half* Wp = WT + (size_t)n0 * DIM + ch * 64;
#pragma unroll
    for (int u = 0; u < 4; ++u) {
        int i = tid + u * 256;               // 1024: 128 rows x 8 chunks
        int row = i >> 3, c16 = i & 7;
        cp_async16(sa + (uint32_t)(row * 144 + c16 * 16),
                   Ap + (size_t)row * DIM + c16 * 8);
        cp_async16(sb + (uint32_t)(row * 144 + c16 * 16),
                   Wp + (size_t)row * DIM + c16 * 8);
    }
}

template <int MODE>
__device__ __forceinline__ void gemm_body_h(
    const __half* __restrict__ A, const __half* __restrict__ WT,
    const float* __restrict__ bias, void* Cout, float bscale, char* smc)
{
    float* sbias = (float*)(smc + OFF_BIAS_B);
    const uint32_t sbase = smem_u32(smc);
    const int tid = threadIdx.x;
    const int wid = tid >> 5, lane = tid & 31;
    const int wm = wid >> 2, wn = wid & 3;
    const int g = lane >> 2, tig = lane & 3;
    const int n0 = blockIdx.x * 128;
    const int m0 = blockIdx.y * 128;

    if (tid < 128) sbias[tid] = bias[n0 + tid] * bscale;

    const uint32_t afoff = (uint32_t)(
        (wm * 64 + ((lane >> 3) & 1) * 8 + (lane & 7)) * 144 +
        ((lane >> 4) & 1) * 16);
    const uint32_t bfoff = (uint32_t)(
        (wn * 32 + ((lane >> 4) & 1) * 8 + (lane & 7)) * 144 +
        ((lane >> 3) & 1) * 16);

    float c[4][4][4];
#pragma unroll
    for (int mt = 0; mt < 4; ++mt)
#pragma unroll
        for (int nt = 0; nt < 4; ++nt)
#pragma unroll
            for (int q = 0; q < 4; ++q) c[mt][nt][q] = 0.f;

    gemm_issue_h(sbase, 0, 0, A, WT, m0, n0, tid);
    CP_COMMIT();
    gemm_issue_h(sbase, 1, 1, A, WT, m0, n0, tid);
    CP_COMMIT();

    for (int ch = 0; ch < 16; ++ch) {
        if (ch == 15) CP_WAIT0(); else CP_WAIT1();
        __syncthreads();
        if (ch < 14) {
            gemm_issue_h(sbase, (ch + 2) % 3, ch + 2, A, WT, m0, n0, tid);
            CP_COMMIT();
        }

        const uint32_t sAb = sbase + (uint32_t)((ch % 3) * STAGE_BYTES);
        const uint32_t sBb = sAb + SB_OFF;

#pragma unroll
        for (int kk = 0; kk < 4; ++kk) {
            uint32_t af[4][4], bf[4][2];
#pragma unroll
            for (int mt = 0; mt < 4; ++mt)
                ldsm_x4(af[mt][0], af[mt][1], af[mt][2], af[mt][3],
                        sAb + afoff + mt * 2304 + kk * 32);
#pragma unroll
            for (int p = 0; p < 2; ++p)
                ldsm_x4(bf[2 * p][0], bf[2 * p][1],
                        bf[2 * p + 1][0], bf[2 * p + 1][1],
                        sBb + bfoff + p * 2304 + kk * 32);
#pragma unroll
            for (int mt = 0; mt < 4; ++mt)
#pragma unroll
                for (int nt = 0; nt < 4; ++nt)
                    mma_f16(c[mt][nt], af[mt][0], af[mt][1], af[mt][2],
                            af[mt][3], bf[nt][0], bf[nt][1]);
        }
    }

#pragma unroll
    for (int mt = 0; mt < 4; ++mt) {
        int row = m0 + wm * 64 + mt * 16 + g;
#pragma unroll
        for (int nt = 0; nt < 4; ++nt) {
            int col = n0 + wn * 32 + nt * 8 + 2 * tig;
            float b0 = sbias[col - n0], b1 = sbias[col - n0 + 1];
            float v00 = c[mt][nt][0] + b0, v01 = c[mt][nt][1] + b1;
            float v10 = c[mt][nt][2] + b0, v11 = c[mt][nt][3] + b1;
            if (MODE == 0) {
                __half* C = (__half*)Cout;
                *(uint32_t*)(C + (size_t)row * DIM + col) = pack_h2(v00, v01);
                *(uint32_t*)(C + (size_t)(row + 8) * DIM + col) =
                    pack_h2(v10, v11);
            } else if (MODE == 1) {
                __half* VT = (__half*)Cout;   // [b][dim][s]
                int bb = row >> 11, ss = row & 2047;
                VT[((size_t)bb * DIM + col) * SEQ + ss] = __float2half(v00);
                VT[((size_t)bb * DIM + col + 1) * SEQ + ss] = __float2half(v01);
                VT[((size_t)bb * DIM + col) * SEQ + ss + 8] = __float2half(v10);
                VT[((size_t)bb * DIM + col + 1) * SEQ + ss + 8] =
                    __float2half(v11);
            } else {
                float* C = (float*)Cout;
                *(float2*)(C + (size_t)row * DIM + col) = make_float2(v00, v01);
                *(float2*)(C + (size_t)(row + 8) * DIM + col) =
                    make_float2(v10, v11);
            }
        }
    }
}

__global__ __launch_bounds__(256, 2) void qkv_gemm_kernel(
    const float* __restrict__ bq, const float* __restrict__ bk,
    const float* __restrict__ bv)
{
    extern __shared__ char smc[];
    const int z = blockIdx.z;
    const __half* A = g_hin + (size_t)z * MROWS * DIM;
    const __half* WT = g_hwt + (size_t)z * DIM * DIM;
    if (z == 0)
        gemm_body_h<0>(A, WT, bq, g_hq, QSCALE, smc);
    else if (z == 1)
        gemm_body_h<0>(A, WT, bk, g_hk, 1.0f, smc);
    else
        gemm_body_h<1>(A, WT, bv, g_vt, 1.0f, smc);
}

__global__ __launch_bounds__(256, 2) void oproj_gemm_kernel(
    const float* __restrict__ bias, float* __restrict__ C)
{
    extern __shared__ char smc[];
    gemm_body_h<2>(g_hctx, g_hwt + (size_t)3 * DIM * DIM, bias, C, 1.0f, smc);
}

// ---------------------------------------------------------------------------
// FA2 attention (proven R10 shape): fp16 MMAs + ldmatrix + bit-packed mask.
// Block = 256 threads (8 warps) x 128 q rows; warp owns 16 q rows.
// ---------------------------------------------------------------------------
#define APH 72                                // halves pitch => 144 B
#define Q_BYTES (128 * APH * 2)               // 18432
#define KV_V_OFF (64 * APH * 2)               // 9216
#define KV_STAGE_B (2 * 64 * APH * 2)         // 18432
#define ATTN_SMEM_BYTES (Q_BYTES + 2 * KV_STAGE_B)   // 55296

__global__ __launch_bounds__(256, 2) void attn_mma_kernel()
{
    extern __shared__ char smc[];
    const uint32_t sbase = smem_u32(smc);

    const int tid = threadIdx.x;
    const int wid = tid >> 5, lane = tid & 31;
    const int g = lane >> 2, tig = lane & 3;
    const int q0 = blockIdx.x * 128;
    const int h = blockIdx.y;
    const int b = blockIdx.z;

    const __half* qb = g_hq + ((size_t)b * SEQ + q0) * DIM + h * HDIM;
    const __half* kb = g_hk + (size_t)b * SEQ * DIM + h * HDIM;
    const __half* vtb = g_vt + ((size_t)b * DIM + h * HDIM) * SEQ;

    // ldmatrix per-lane address offsets.
    const uint32_t qoff = (uint32_t)(
        (wid * 16 + ((lane >> 3) & 1) * 8 + (lane & 7)) * 144 +
        ((lane >> 4) & 1) * 16);
    const uint32_t bfoff = (uint32_t)(
        (((lane >> 4) & 1) * 8 + (lane & 7)) * 144 +
        ((lane >> 3) & 1) * 16);

    // Prologue: stage Q (128x64) + K/V tile 0.
#pragma unroll
    for (int u = 0; u < 4; ++u) {
        int i = tid + u * 256;               // 1024: 128 rows x 8 chunks
        int row = i >> 3, c16 = i & 7;
        cp_async16(sbase + (uint32_t)(row * 144 + c16 * 16),
                   qb + (size_t)row * DIM + c16 * 8);
    }
    {
        uint32_t kst = sbase + Q_BYTES;
        uint32_t vst = kst + KV_V_OFF;
#pragma unroll
        for (int u = 0; u < 2; ++u) {
            int i = tid + u * 256;           // 512: 64 rows x 8 chunks
            int row = i >> 3, c16 = i & 7;
            cp_async16(kst + (uint32_t)(row * 144 + c16 * 16),
                       kb + (size_t)row * DIM + c16 * 8);
            cp_async16(vst + (uint32_t)(row * 144 + c16 * 16),
                       vtb + (size_t)row * SEQ + c16 * 8);
        }
    }
    CP_COMMIT();

    const int r0 = wid * 16 + g;
    float m0 = -1e30f, m1 = -1e30f, l0 = 0.f, l1 = 0.f;
    float o[8][4];
#pragma unroll
    for (int nt = 0; nt < 8; ++nt)
#pragma unroll
        for (int q = 0; q < 4; ++q) o[nt][q] = 0.f;

    // Bit-packed mask rows for this thread's two q rows (64 words/row).
    const uint32_t* bmr0 = g_mb + (size_t)(q0 + r0) * (SEQ / 32);
    const uint32_t* bmr1 = bmr0 + 8 * (SEQ / 32);

    for (int kt = 0; kt < SEQ / 64; ++kt) {
        const int kg0 = kt * 64;

        // Mask bits for this tile (hoisted above the wait; L2-resident).
        uint2 w0 = *(const uint2*)(bmr0 + (kg0 >> 5));
        uint2 w1 = *(const uint2*)(bmr1 + (kg0 >> 5));

        CP_WAIT0();
        __syncthreads();

        // Prefetch next K/V tile.
        if (kt < SEQ / 64 - 1) {
            int s = (kt + 1) & 1;
            int kg = (kt + 1) * 64;
            uint32_t kst = sbase + Q_BYTES + (uint32_t)(s * KV_STAGE_B);
            uint32_t vst = kst + KV_V_OFF;
#pragma unroll
            for (int u = 0; u < 2; ++u) {
                int i = tid + u * 256;
                int row = i >> 3, c16 = i & 7;
                cp_async16(kst + (uint32_t)(row * 144 + c16 * 16),
                           kb + (size_t)(kg + row) * DIM + c16 * 8);
                cp_async16(vst + (uint32_t)(row * 144 + c16 * 16),
                           vtb + (size_t)row * SEQ + kg + c16 * 8);
            }
            CP_COMMIT();
        }

        const uint32_t kbase_s = sbase + Q_BYTES
                                 + (uint32_t)((kt & 1) * KV_STAGE_B);
        const uint32_t vbase_s = kbase_s + KV_V_OFF;

        // S = Q @ K^T : 4 k16 steps, 8 n-tiles, S in registers.
        float c[8][4];
#pragma unroll
        for (int nt = 0; nt < 8; ++nt)
#pragma unroll
            for (int q = 0; q < 4; ++q) c[nt][q] = 0.f;

#pragma unroll
        for (int kk = 0; kk < 4; ++kk) {
            uint32_t a0, a1, a2, a3;
            ldsm_x4(a0, a1, a2, a3, sbase + qoff + kk * 32);
#pragma unroll
            for (int p = 0; p < 4; ++p) {
                uint32_t b0, b1, b2, b3;
                ldsm_x4(b0, b1, b2, b3,
                        kbase_s + bfoff + p * 2304 + kk * 32);
                mma_f16(c[2 * p], a0, a1, a2, a3, b0, b1);
                mma_f16(c[2 * p + 1], a0, a1, a2, a3, b2, b3);
            }
        }

        // Mask (bit tests) + row max (scores in log2 units).
        float mx0 = -1e30f, mx1 = -1e30f;
#pragma unroll
        for (int nt = 0; nt < 8; ++nt) {
            uint32_t wa = (nt < 4) ? w0.x : w0.y;
            uint32_t wb = (nt < 4) ? w1.x : w1.y;
            int sh = (nt & 3) * 8 + 2 * tig;
            uint32_t ta = wa >> sh, tb = wb >> sh;
            c[nt][0] = (ta & 1u) ? c[nt][0] : -1e30f;
            c[nt][1] = (ta & 2u) ? c[nt][1] : -1e30f;
            c[nt][2] = (tb & 1u) ? c[nt][2] : -1e30f;
            c[nt][3] = (tb & 2u) ? c[nt][3] : -1e30f;
            mx0 = fmaxf(mx0, fmaxf(c[nt][0], c[nt][1]));
            mx1 = fmaxf(mx1, fmaxf(c[nt][2], c[nt][3]));
        }
        mx0 = fmaxf(mx0, __shfl_xor_sync(0xffffffffu, mx0, 1));
        mx0 = fmaxf(mx0, __shfl_xor_sync(0xffffffffu, mx0, 2));
        mx1 = fmaxf(mx1, __shfl_xor_sync(0xffffffffu, mx1, 1));
        mx1 = fmaxf(mx1, __shfl_xor_sync(0xffffffffu, mx1, 2));

        float mn0 = fmaxf(m0, mx0), mn1 = fmaxf(m1, mx1);
        float al0 = ex2(m0 - mn0), al1 = ex2(m1 - mn1);
        float s0 = 0.f, s1 = 0.f;
#pragma unroll
        for (int nt = 0; nt < 8; ++nt) {
            float p0 = ex2(c[nt][0] - mn0);
            float p1 = ex2(c[nt][1] - mn0);
            float p2 = ex2(c[nt][2] - mn1);
            float p3 = ex2(c[nt][3] - mn1);
            s0 += p0 + p1;
            s1 += p2 + p3;
            c[nt][0] = p0; c[nt][1] = p1; c[nt][2] = p2; c[nt][3] = p3;
        }
        s0 += __shfl_xor_sync(0xffffffffu, s0, 1);
        s0 += __shfl_xor_sync(0xffffffffu, s0, 2);
        s1 += __shfl_xor_sync(0xffffffffu, s1, 1);
        s1 += __shfl_xor_sync(0xffffffffu, s1, 2);
        l0 = l0 * al0 + s0;
        l1 = l1 * al1 + s1;
        m0 = mn0; m1 = mn1;

#pragma unroll
        for (int nt = 0; nt < 8; ++nt) {
            o[nt][0] *= al0; o[nt][1] *= al0;
            o[nt][2] *= al1; o[nt][3] *= al1;
        }

        // O += P @ V: A-frags come straight from the S C-frags (k16).
#pragma unroll
        for (int kk = 0; kk < 4; ++kk) {
            uint32_t a0 = pack_h2(c[2 * kk][0], c[2 * kk][1]);
            uint32_t a1 = pack_h2(c[2 * kk][2], c[2 * kk][3]);
            uint32_t a2 = pack_h2(c[2 * kk + 1][0], c[2 * kk + 1][1]);
            uint32_t a3 = pack_h2(c[2 * kk + 1][2], c[2 * kk + 1][3]);
#pragma unroll
            for (int p = 0; p < 4; ++p) {
                uint32_t b0, b1, b2, b3;
                ldsm_x4(b0, b1, b2, b3,
                        vbase_s + bfoff + p * 2304 + kk * 32);
                mma_f16(o[2 * p], a0, a1, a2, a3, b0, b1);
                mma_f16(o[2 * p + 1], a0, a1, a2, a3, b2, b3);
            }
        }
    }

    // Final normalize + store fp16 (merged-head layout).
    float inv0 = 1.f / l0, inv1 = 1.f / l1;
    __half* od = g_hctx + ((size_t)b * SEQ + q0 + r0) * DIM + h * HDIM;
#pragma unroll
    for (int nt = 0; nt < 8; ++nt) {
        *(uint32_t*)(od + nt * 8 + 2 * tig) =
            pack_h2(o[nt][0] * inv0, o[nt][1] * inv0);
        *(uint32_t*)(od + (size_t)8 * DIM + nt * 8 + 2 * tig) =
            pack_h2(o[nt][2] * inv1, o[nt][3] * inv1);
    }
}

// ---------------------------------------------------------------------------
// Launch
// ---------------------------------------------------------------------------
extern "C" void kernel_launch(void* const* d_in, const int* in_sizes, int n_in,
                              void* d_out, int out_size)
{
    (void)in_sizes; (void)n_in; (void)out_size;
    const float* Q  = (const float*)d_in[0];
    const float* K  = (const float*)d_in[1];
    const float* V  = (const float*)d_in[2];
    const int* mask = (const int*)d_in[3];
    const float* Wq = (const float*)d_in[4];
    const float* bq = (const float*)d_in[5];
    const float* Wk = (const float*)d_in[6];
    const float* bk = (const float*)d_in[7];
    const float* Wv = (const float*)d_in[8];
    const float* bv = (const float*)d_in[9];
    const float* Wo = (const float*)d_in[10];
    const float* bo = (const float*)d_in[11];
    float* out = (float*)d_out;

    cudaFuncSetAttribute(qkv_gemm_kernel,
                         cudaFuncAttributeMaxDynamicSharedMemorySize,
                         GEMM_SMEM_BYTES);
    cudaFuncSetAttribute(oproj_gemm_kernel,
                         cudaFuncAttributeMaxDynamicSharedMemorySize,
                         GEMM_SMEM_BYTES);
    cudaFuncSetAttribute(attn_mma_kernel,
                         cudaFuncAttributeMaxDynamicSharedMemorySize,
                         ATTN_SMEM_BYTES);

    // Convert inputs and weights to fp16; pack the mask to bits.
    dim3 cigrid(MROWS * DIM / (256 * 8), 3);
    convert_in_kernel<<<cigrid, 256>>>(Q, K, V);
    pack_mask_kernel<<<SEQ * (SEQ / 32) / 256, 256>>>(mask);
    dim3 cwgrid(32, 32, 4), cwblk(32, 8);
    convert_wt_kernel<<<cwgrid, cwblk>>>(Wq, Wk, Wv, Wo);

    // Batched QKV projections.
    dim3 qkvgrid(DIM / 128, MROWS / 128, 3);
    qkv_gemm_kernel<<<qkvgrid, 256, GEMM_SMEM_BYTES>>>(bq, bk, bv);

    // Attention.
    dim3 agrid(SEQ / 128, NHEAD, BSZ);  // (16, 16, 2)
    attn_mma_kernel<<<agrid, 256, ATTN_SMEM_BYTES>>>();

    // Output projection.
    dim3 ggrid(DIM / 128, MROWS / 128);
    oproj_gemm_kernel<<<ggrid, 256, GEMM_SMEM_BYTES>>>(bo, out);
}

// round 14
// speedup vs baseline: 1.1358x; 1.0284x over previous
#include <cuda_runtime.h>
#include <cuda_fp16.h>
#include <cstdint>

#define BSZ 2
#define SEQ 2048
#define DIM 1024
#define NHEAD 16
#define HDIM 64
#define MROWS (BSZ * SEQ)   // 4096

// Scratch (allocation-free requirement -> __device__ globals), all fp16.
__device__ __half g_hin[(size_t)3 * MROWS * DIM];  // converted inputs Q,K,V
__device__ __half g_hwt[(size_t)4 * DIM * DIM];    // W^T fp16 (Wq pre-scaled)
__device__ __half g_hq[(size_t)MROWS * DIM];       // q proj (scaled)
__device__ __half g_hk[(size_t)MROWS * DIM];       // k proj
__device__ __half g_vt[(size_t)BSZ * DIM * SEQ];   // v proj, transposed [b][dim][s]
__device__ __half g_hctx[(size_t)MROWS * DIM];     // attention output
__device__ uint32_t g_mb[(size_t)SEQ * (SEQ / 32)]; // mask bit-packed, 64 w/row

// 0.125 (1/sqrt(64)) * log2(e): folded into Wq/bq so softmax can use exp2.
#define QSCALE 0.1803368801111137f

__device__ __forceinline__ uint32_t smem_u32(const void* p) {
    uint32_t a;
    asm("{ .reg .u64 t; cvta.to.shared.u64 t, %1; cvt.u32.u64 %0, t; }"
        : "=r"(a) : "l"(p));
    return a;
}

__device__ __forceinline__ void cp_async16(uint32_t dst, const void* src) {
    asm volatile("cp.async.cg.shared.global [%0], [%1], 16;"
                 :: "r"(dst), "l"(src));
}
#define CP_COMMIT() asm volatile("cp.async.commit_group;" ::: "memory")
#define CP_WAIT0()  asm volatile("cp.async.wait_group 0;" ::: "memory")
#define CP_WAIT1()  asm volatile("cp.async.wait_group 1;" ::: "memory")

__device__ __forceinline__ uint32_t pack_h2(float lo, float hi) {
    __half2 h = __floats2half2_rn(lo, hi);
    return *(uint32_t*)&h;
}

__device__ __forceinline__ float ex2(float x) {
    float r;
    asm("ex2.approx.ftz.f32 %0, %1;" : "=f"(r) : "f"(x));
    return r;
}

// ldmatrix x4: loads four 8x8 b16 tiles.
__device__ __forceinline__ void ldsm_x4(uint32_t& r0, uint32_t& r1,
                                        uint32_t& r2, uint32_t& r3,
                                        uint32_t addr) {
    asm volatile("ldmatrix.sync.aligned.m8n8.x4.shared.b16 "
                 "{%0,%1,%2,%3}, [%4];"
                 : "=r"(r0), "=r"(r1), "=r"(r2), "=r"(r3) : "r"(addr));
}

// m16n8k16 fp16 HMMA, fp32 accumulate.
__device__ __forceinline__ void mma_f16(float c[4],
                                        uint32_t a0, uint32_t a1,
                                        uint32_t a2, uint32_t a3,
                                        uint32_t b0, uint32_t b1) {
    asm volatile(
        "mma.sync.aligned.m16n8k16.row.col.f32.f16.f16.f32 "
        "{%0,%1,%2,%3}, {%4,%5,%6,%7}, {%8,%9}, {%0,%1,%2,%3};"
        : "+f"(c[0]), "+f"(c[1]), "+f"(c[2]), "+f"(c[3])
        : "r"(a0), "r"(a1), "r"(a2), "r"(a3), "r"(b0), "r"(b1));
}

// ---------------------------------------------------------------------------
// Fused prologue (one launch, branch on blockIdx.z):
//   z=0..2 : convert inputs Q/K/V fp32 -> fp16         (grid.x = 2048)
//   z=3    : pack mask to bits                          (grid.x = 512 used)
//   z=4..7 : weight transpose+convert (z-4 selects W)   (grid.x = 1024 used)
// ---------------------------------------------------------------------------
__global__ __launch_bounds__(256) void prologue_kernel(
    const float* __restrict__ Q, const float* __restrict__ K,
    const float* __restrict__ V, const int* __restrict__ mask,
    const float* __restrict__ Wq, const float* __restrict__ Wk,
    const float* __restrict__ Wv, const float* __restrict__ Wo)
{
    const int z = blockIdx.z;
    if (z < 3) {
        const float* src = (z == 0) ? Q : (z == 1) ? K : V;
        size_t off = ((size_t)blockIdx.x * 256 + threadIdx.x) * 8;
        float4 v0 = *(const float4*)(src + off);
        float4 v1 = *(const float4*)(src + off + 4);
        __half2* dst = (__half2*)(g_hin + (size_t)z * MROWS * DIM + off);
        uint4 pk;
        pk.x = pack_h2(v0.x, v0.y);
        pk.y = pack_h2(v0.z, v0.w);
        pk.z = pack_h2(v1.x, v1.y);
        pk.w = pack_h2(v1.z, v1.w);
        *(uint4*)dst = pk;
    } else if (z == 3) {
        if (blockIdx.x >= SEQ * (SEQ / 32) / 256) return;
        int idx = blockIdx.x * 256 + threadIdx.x;
        const int* src = mask + (size_t)idx * 32;
        uint32_t bits = 0;
#pragma unroll
        for (int u = 0; u < 8; ++u) {
            int4 v = *(const int4*)(src + u * 4);
            bits |= (v.x ? 1u : 0u) << (u * 4);
            bits |= (v.y ? 1u : 0u) << (u * 4 + 1);
            bits |= (v.z ? 1u : 0u) << (u * 4 + 2);
            bits |= (v.w ? 1u : 0u) << (u * 4 + 3);
        }
        g_mb[idx] = bits;
    } else {
        __shared__ float t[32][33];
        const int wz = z - 4;
        if (blockIdx.x >= 32 * 32) return;
        const float* W = (wz == 0) ? Wq : (wz == 1) ? Wk : (wz == 2) ? Wv : Wo;
        const float scale = (wz == 0) ? QSCALE : 1.0f;
        __half* WT = g_hwt + (size_t)wz * DIM * DIM;
        const int bx = (blockIdx.x & 31) * 32;   // n
        const int by = (blockIdx.x >> 5) * 32;   // k
        const int x = threadIdx.x & 31, y = threadIdx.x >> 5;
#pragma unroll
        for (int j = 0; j < 32; j += 8)
            t[y + j][x] = W[(size_t)(by + y + j) * DIM + bx + x];
        __syncthreads();
#pragma unroll
        for (int j = 0; j < 32; j += 8)
            WT[(size_t)(bx + y + j) * DIM + by + x] =
                __float2half(t[x][y + j] * scale);
    }
}

// ---------------------------------------------------------------------------
// fp16 GEMM (proven R12 pipeline): 128x128 tile, BK=64 (4 k16 steps/chunk),
// cp.async 3-stage, WAIT -> barrier -> prefetch, ldmatrix fragment loads.
// MODE 0: half row-major out.  MODE 1: half transposed out ([b][dim][s]).
// MODE 2: float row-major out.
// ---------------------------------------------------------------------------
#define GPAH 72                              // halves pitch => 144 B
#define SB_OFF (128 * GPAH * 2)              // 18432 B: B within stage
#define STAGE_BYTES (2 * 128 * GPAH * 2)     // 36864 B
#define OFF_BIAS_B (3 * STAGE_BYTES)         // 110592
#define GEMM_SMEM_BYTES (OFF_BIAS_B + 128 * 4)   // 111104

__device__ __forceinline__ void gemm_issue_h(
    uint32_t sbase, int s, int ch, const __half* __restrict__ A,
    const __half* __restrict__ WT, int m0, int n0, int tid)
{
    uint32_t sa = sbase + (uint32_t)(s * STAGE_BYTES);
    uint32_t sb = sa + SB_OFF;
    const __half* Ap = A + (size_t)m0 * DIM + ch * 64;
    const __half* Wp = WT + (size_t)n0 * DIM + ch * 64;
#pragma unroll
    for (int u = 0; u < 4; ++u) {
        int i = tid + u * 256;               // 1024: 128 rows x 8 chunks
        int row = i >> 3, c16 = i & 7;
        cp_async16(sa + (uint32_t)(row * 144 + c16 * 16),
                   Ap + (size_t)row * DIM + c16 * 8);
        cp_async16(sb + (uint32_t)(row * 144 + c16 * 16),
                   Wp + (size_t)row * DIM + c16 * 8);
    }
}

template <int MODE>
__device__ __forceinline__ void gemm_body_h(
    const __half* __restrict__ A, const __half* __restrict__ WT,
    const float* __restrict__ bias, void* Cout, float bscale, char* smc)
{
    float* sbias = (float*)(smc + OFF_BIAS_B);
    const uint32_t sbase = smem_u32(smc);
    const int tid = threadIdx.x;
    const int wid = tid >> 5, lane = tid & 31;
    const int wm = wid >> 2, wn = wid & 3;
    const int g = lane >> 2, tig = lane & 3;
    const int n0 = blockIdx.x * 128;
    const int m0 = blockIdx.y * 128;

    if (tid < 128) sbias[tid] = bias[n0 + tid] * bscale;

    const uint32_t afoff = (uint32_t)(
        (wm * 64 + ((lane >> 3) & 1) * 8 + (lane & 7)) * 144 +
        ((lane >> 4) & 1) * 16);
    const uint32_t bfoff = (uint32_t)(
        (wn * 32 + ((lane >> 4) & 1) * 8 + (lane & 7)) * 144 +
        ((lane >> 3) & 1) * 16);

    float c[4][4][4];
#pragma unroll
    for (int mt = 0; mt < 4; ++mt)
#pragma unroll
        for (int nt = 0; nt < 4; ++nt)
#pragma unroll
            for (int q = 0; q < 4; ++q) c[mt][nt][q] = 0.f;

    gemm_issue_h(sbase, 0, 0, A, WT, m0, n0, tid);
    CP_COMMIT();
    gemm_issue_h(sbase, 1, 1, A, WT, m0, n0, tid);
    CP_COMMIT();

    for (int ch = 0; ch < 16; ++ch) {
        if (ch == 15) CP_WAIT0(); else CP_WAIT1();
        __syncthreads();
        if (ch < 14) {
            gemm_issue_h(sbase, (ch + 2) % 3, ch + 2, A, WT, m0, n0, tid);
            CP_COMMIT();
        }

        const uint32_t sAb = sbase + (uint32_t)((ch % 3) * STAGE_BYTES);
        const uint32_t sBb = sAb + SB_OFF;

#pragma unroll
        for (int kk = 0; kk < 4; ++kk) {
            uint32_t af[4][4], bf[4][2];
#pragma unroll
            for (int mt = 0; mt < 4; ++mt)
                ldsm_x4(af[mt][0], af[mt][1], af[mt][2], af[mt][3],
                        sAb + afoff + mt * 2304 + kk * 32);
#pragma unroll
            for (int p = 0; p < 2; ++p)
                ldsm_x4(bf[2 * p][0], bf[2 * p][1],
                        bf[2 * p + 1][0], bf[2 * p + 1][1],
                        sBb + bfoff + p * 2304 + kk * 32);
#pragma unroll
            for (int mt = 0; mt < 4; ++mt)
#pragma unroll
                for (int nt = 0; nt < 4; ++nt)
                    mma_f16(c[mt][nt], af[mt][0], af[mt][1], af[mt][2],
                            af[mt][3], bf[nt][0], bf[nt][1]);
        }
    }

#pragma unroll
    for (int mt = 0; mt < 4; ++mt) {
        int row = m0 + wm * 64 + mt * 16 + g;
#pragma unroll
        for (int nt = 0; nt < 4; ++nt) {
            int col = n0 + wn * 32 + nt * 8 + 2 * tig;
            float b0 = sbias[col - n0], b1 = sbias[col - n0 + 1];
            float v00 = c[mt][nt][0] + b0, v01 = c[mt][nt][1] + b1;
            float v10 = c[mt][nt][2] + b0, v11 = c[mt][nt][3] + b1;
            if (MODE == 0) {
                __half* C = (__half*)Cout;
                *(uint32_t*)(C + (size_t)row * DIM + col) = pack_h2(v00, v01);
                *(uint32_t*)(C + (size_t)(row + 8) * DIM + col) =
                    pack_h2(v10, v11);
            } else if (MODE == 1) {
                __half* VT = (__half*)Cout;   // [b][dim][s]
                int bb = row >> 11, ss = row & 2047;
                VT[((size_t)bb * DIM + col) * SEQ + ss] = __float2half(v00);
                VT[((size_t)bb * DIM + col + 1) * SEQ + ss] = __float2half(v01);
                VT[((size_t)bb * DIM + col) * SEQ + ss + 8] = __float2half(v10);
                VT[((size_t)bb * DIM + col + 1) * SEQ + ss + 8] =
                    __float2half(v11);
            } else {
                float* C = (float*)Cout;
                *(float2*)(C + (size_t)row * DIM + col) = make_float2(v00, v01);
                *(float2*)(C + (size_t)(row + 8) * DIM + col) =
                    make_float2(v10, v11);
            }
        }
    }
}

__global__ __launch_bounds__(256, 2) void qkv_gemm_kernel(
    const float* __restrict__ bq, const float* __restrict__ bk,
    const float* __restrict__ bv)
{
    extern __shared__ char smc[];
    const int z = blockIdx.z;
    const __half* A = g_hin + (size_t)z * MROWS * DIM;
    const __half* WT = g_hwt + (size_t)z * DIM * DIM;
    if (z == 0)
        gemm_body_h<0>(A, WT, bq, g_hq, QSCALE, smc);
    else if (z == 1)
        gemm_body_h<0>(A, WT, bk, g_hk, 1.0f, smc);
    else
        gemm_body_h<1>(A, WT, bv, g_vt, 1.0f, smc);
}

__global__ __launch_bounds__(256, 2) void oproj_gemm_kernel(
    const float* __restrict__ bias, float* __restrict__ C)
{
    extern __shared__ char smc[];
    gemm_body_h<2>(g_hctx, g_hwt + (size_t)3 * DIM * DIM, bias, C, 1.0f, smc);
}

// ---------------------------------------------------------------------------
// FA2 attention (proven R12 pipeline): fp16 MMAs + ldmatrix + bit-packed mask.
// Block = 256 threads (8 warps) x 128 q rows; warp owns 16 q rows.
// ---------------------------------------------------------------------------
#define APH 72                                // halves pitch => 144 B
#define Q_BYTES (128 * APH * 2)               // 18432
#define KV_V_OFF (64 * APH * 2)               // 9216
#define KV_STAGE_B (2 * 64 * APH * 2)         // 18432
#define ATTN_SMEM_BYTES (Q_BYTES + 2 * KV_STAGE_B)   // 55296

__global__ __launch_bounds__(256, 2) void attn_mma_kernel()
{
    extern __shared__ char smc[];
    const uint32_t sbase = smem_u32(smc);

    const int tid = threadIdx.x;
    const int wid = tid >> 5, lane = tid & 31;
    const int g = lane >> 2, tig = lane & 3;
    const int q0 = blockIdx.x * 128;
    const int h = blockIdx.y;
    const int b = blockIdx.z;

    const __half* qb = g_hq + ((size_t)b * SEQ + q0) * DIM + h * HDIM;
    const __half* kb = g_hk + (size_t)b * SEQ * DIM + h * HDIM;
    const __half* vtb = g_vt + ((size_t)b * DIM + h * HDIM) * SEQ;

    // ldmatrix per-lane address offsets.
    const uint32_t qoff = (uint32_t)(
        (wid * 16 + ((lane >> 3) & 1) * 8 + (lane & 7)) * 144 +
        ((lane >> 4) & 1) * 16);
    const uint32_t bfoff = (uint32_t)(
        (((lane >> 4) & 1) * 8 + (lane & 7)) * 144 +
        ((lane >> 3) & 1) * 16);

    // Prologue: stage Q (128x64) + K/V tile 0.
#pragma unroll
    for (int u = 0; u < 4; ++u) {
        int i = tid + u * 256;               // 1024: 128 rows x 8 chunks
        int row = i >> 3, c16 = i & 7;
        cp_async16(sbase + (uint32_t)(row * 144 + c16 * 16),
                   qb + (size_t)row * DIM + c16 * 8);
    }
    {
        uint32_t kst = sbase + Q_BYTES;
        uint32_t vst = kst + KV_V_OFF;
#pragma unroll
        for (int u = 0; u < 2; ++u) {
            int i = tid + u * 256;           // 512: 64 rows x 8 chunks
            int row = i >> 3, c16 = i & 7;
            cp_async16(kst + (uint32_t)(row * 144 + c16 * 16),
                       kb + (size_t)row * DIM + c16 * 8);
            cp_async16(vst + (uint32_t)(row * 144 + c16 * 16),
                       vtb + (size_t)row * SEQ + c16 * 8);
        }
    }
    CP_COMMIT();

    const int r0 = wid * 16 + g;
    float m0 = -1e30f, m1 = -1e30f, l0 = 0.f, l1 = 0.f;
    float o[8][4];
#pragma unroll
    for (int nt = 0; nt < 8; ++nt)
#pragma unroll
        for (int q = 0; q < 4; ++q) o[nt][q] = 0.f;

    // Bit-packed mask rows for this thread's two q rows (64 words/row).
    const uint32_t* bmr0 = g_mb + (size_t)(q0 + r0) * (SEQ / 32);
    const uint32_t* bmr1 = bmr0 + 8 * (SEQ / 32);

    for (int kt = 0; kt < SEQ / 64; ++kt) {
        const int kg0 = kt * 64;

        // Mask bits for this tile (L2-resident; hides under MMAs).
        uint2 w0 = *(const uint2*)(bmr0 + (kg0 >> 5));
        uint2 w1 = *(const uint2*)(bmr1 + (kg0 >> 5));

        CP_WAIT0();
        __syncthreads();

        // Prefetch next K/V tile.
        if (kt < SEQ / 64 - 1) {
            int s = (kt + 1) & 1;
            int kg = (kt + 1) * 64;
            uint32_t kst = sbase + Q_BYTES + (uint32_t)(s * KV_STAGE_B);
            uint32_t vst = kst + KV_V_OFF;
#pragma unroll
            for (int u = 0; u < 2; ++u) {
                int i = tid + u * 256;
                int row = i >> 3, c16 = i & 7;
                cp_async16(kst + (uint32_t)(row * 144 + c16 * 16),
                           kb + (size_t)(kg + row) * DIM + c16 * 8);
                cp_async16(vst + (uint32_t)(row * 144 + c16 * 16),
                           vtb + (size_t)row * SEQ + kg + c16 * 8);
            }
            CP_COMMIT();
        }

        const uint32_t kbase_s = sbase + Q_BYTES
                                 + (uint32_t)((kt & 1) * KV_STAGE_B);
        const uint32_t vbase_s = kbase_s + KV_V_OFF;

        // S = Q @ K^T : 4 k16 steps, 8 n-tiles, S in registers.
        float c[8][4];
#pragma unroll
        for (int nt = 0; nt < 8; ++nt)
#pragma unroll
            for (int q = 0; q < 4; ++q) c[nt][q] = 0.f;

#pragma unroll
        for (int kk = 0; kk < 4; ++kk) {
            uint32_t a0, a1, a2, a3;
            ldsm_x4(a0, a1, a2, a3, sbase + qoff + kk * 32);
#pragma unroll
            for (int p = 0; p < 4; ++p) {
                uint32_t b0, b1, b2, b3;
                ldsm_x4(b0, b1, b2, b3,
                        kbase_s + bfoff + p * 2304 + kk * 32);
                mma_f16(c[2 * p], a0, a1, a2, a3, b0, b1);
                mma_f16(c[2 * p + 1], a0, a1, a2, a3, b2, b3);
            }
        }

        // Mask (bit tests) + row max (scores in log2 units).
        float mx0 = -1e30f, mx1 = -1e30f;
#pragma unroll
        for (int nt = 0; nt < 8; ++nt) {
            uint32_t wa = (nt < 4) ? w0.x : w0.y;
            uint32_t wb = (nt < 4) ? w1.x : w1.y;
            int sh = (nt & 3) * 8 + 2 * tig;
            uint32_t ta = wa >> sh, tb = wb >> sh;
            c[nt][0] = (ta & 1u) ? c[nt][0] : -1e30f;
            c[nt][1] = (ta & 2u) ? c[nt][1] : -1e30f;
            c[nt][2] = (tb & 1u) ? c[nt][2] : -1e30f;
            c[nt][3] = (tb & 2u) ? c[nt][3] : -1e30f;
            mx0 = fmaxf(mx0, fmaxf(c[nt][0], c[nt][1]));
            mx1 = fmaxf(mx1, fmaxf(c[nt][2], c[nt][3]));
        }
        mx0 = fmaxf(mx0, __shfl_xor_sync(0xffffffffu, mx0, 1));
        mx0 = fmaxf(mx0, __shfl_xor_sync(0xffffffffu, mx0, 2));
        mx1 = fmaxf(mx1, __shfl_xor_sync(0xffffffffu, mx1, 1));
        mx1 = fmaxf(mx1, __shfl_xor_sync(0xffffffffu, mx1, 2));

        float mn0 = fmaxf(m0, mx0), mn1 = fmaxf(m1, mx1);
        float al0 = ex2(m0 - mn0), al1 = ex2(m1 - mn1);
        float s0 = 0.f, s1 = 0.f;
#pragma unroll
        for (int nt = 0; nt < 8; ++nt) {
            float p0 = ex2(c[nt][0] - mn0);
            float p1 = ex2(c[nt][1] - mn0);
            float p2 = ex2(c[nt][2] - mn1);
            float p3 = ex2(c[nt][3] - mn1);
            s0 += p0 + p1;
            s1 += p2 + p3;
            c[nt][0] = p0; c[nt][1] = p1; c[nt][2] = p2; c[nt][3] = p3;
        }
        s0 += __shfl_xor_sync(0xffffffffu, s0, 1);
        s0 += __shfl_xor_sync(0xffffffffu, s0, 2);
        s1 += __shfl_xor_sync(0xffffffffu, s1, 1);
        s1 += __shfl_xor_sync(0xffffffffu, s1, 2);
        l0 = l0 * al0 + s0;
        l1 = l1 * al1 + s1;
        m0 = mn0; m1 = mn1;

#pragma unroll
        for (int nt = 0; nt < 8; ++nt) {
            o[nt][0] *= al0; o[nt][1] *= al0;
            o[nt][2] *= al1; o[nt][3] *= al1;
        }

        // O += P @ V: A-frags come straight from the S C-frags (k16).
#pragma unroll
        for (int kk = 0; kk < 4; ++kk) {
            uint32_t a0 = pack_h2(c[2 * kk][0], c[2 * kk][1]);
            uint32_t a1 = pack_h2(c[2 * kk][2], c[2 * kk][3]);
            uint32_t a2 = pack_h2(c[2 * kk + 1][0], c[2 * kk + 1][1]);
            uint32_t a3 = pack_h2(c[2 * kk + 1][2], c[2 * kk + 1][3]);
#pragma unroll
            for (int p = 0; p < 4; ++p) {
                uint32_t b0, b1, b2, b3;
                ldsm_x4(b0, b1, b2, b3,
                        vbase_s + bfoff + p * 2304 + kk * 32);
                mma_f16(o[2 * p], a0, a1, a2, a3, b0, b1);
                mma_f16(o[2 * p + 1], a0, a1, a2, a3, b2, b3);
            }
        }
    }

    // Final normalize + store fp16 (merged-head layout).
    float inv0 = 1.f / l0, inv1 = 1.f / l1;
    __half* od = g_hctx + ((size_t)b * SEQ + q0 + r0) * DIM + h * HDIM;
#pragma unroll
    for (int nt = 0; nt < 8; ++nt) {
        *(uint32_t*)(od + nt * 8 + 2 * tig) =
            pack_h2(o[nt][0] * inv0, o[nt][1] * inv0);
        *(uint32_t*)(od + (size_t)8 * DIM + nt * 8 + 2 * tig) =
            pack_h2(o[nt][2] * inv1, o[nt][3] * inv1);
    }
}

// ---------------------------------------------------------------------------
// Launch
// ---------------------------------------------------------------------------
extern "C" void kernel_launch(void* const* d_in, const int* in_sizes, int n_in,
                              void* d_out, int out_size)
{
    (void)in_sizes; (void)n_in; (void)out_size;
    const float* Q  = (const float*)d_in[0];
    const float* K  = (const float*)d_in[1];
    const float* V  = (const float*)d_in[2];
    const int* mask = (const int*)d_in[3];
    const float* Wq = (const float*)d_in[4];
    const float* bq = (const float*)d_in[5];
    const float* Wk = (const float*)d_in[6];
    const float* bk = (const float*)d_in[7];
    const float* Wv = (const float*)d_in[8];
    const float* bv = (const float*)d_in[9];
    const float* Wo = (const float*)d_in[10];
    const float* bo = (const float*)d_in[11];
    float* out = (float*)d_out;

    cudaFuncSetAttribute(qkv_gemm_kernel,
                         cudaFuncAttributeMaxDynamicSharedMemorySize,
                         GEMM_SMEM_BYTES);
    cudaFuncSetAttribute(oproj_gemm_kernel,
                         cudaFuncAttributeMaxDynamicSharedMemorySize,
                         GEMM_SMEM_BYTES);
    cudaFuncSetAttribute(attn_mma_kernel,
                         cudaFuncAttributeMaxDynamicSharedMemorySize,
                         ATTN_SMEM_BYTES);

    // Fused prologue: input converts (z=0..2), mask pack (z=3), W^T (z=4..7).
    dim3 pgrid(MROWS * DIM / (256 * 8), 1, 8);
    prologue_kernel<<<pgrid, 256>>>(Q, K, V, mask, Wq, Wk, Wv, Wo);

    // Batched QKV projections.
    dim3 qkvgrid(DIM / 128, MROWS / 128, 3);
    qkv_gemm_kernel<<<qkvgrid, 256, GEMM_SMEM_BYTES>>>(bq, bk, bv);

    // Attention.
    dim3 agrid(SEQ / 128, NHEAD, BSZ);  // (16, 16, 2)
    attn_mma_kernel<<<agrid, 256, ATTN_SMEM_BYTES>>>();

    // Output projection.
    dim3 ggrid(DIM / 128, MROWS / 128);
    oproj_gemm_kernel<<<ggrid, 256, GEMM_SMEM_BYTES>>>(bo, out);
}

// round 16
// speedup vs baseline: 1.1359x; 1.0001x over previous
#include <cuda_runtime.h>
#include <cuda_fp16.h>
#include <cstdint>

#define BSZ 2
#define SEQ 2048
#define DIM 1024
#define NHEAD 16
#define HDIM 64
#define MROWS (BSZ * SEQ)   // 4096

// Scratch (allocation-free requirement -> __device__ globals), all fp16.
__device__ __half g_hin[(size_t)3 * MROWS * DIM];  // converted inputs Q,K,V
__device__ __half g_hwt[(size_t)4 * DIM * DIM];    // W^T fp16 (Wq pre-scaled)
__device__ __half g_hq[(size_t)MROWS * DIM];       // q proj (scaled)
__device__ __half g_hk[(size_t)MROWS * DIM];       // k proj
__device__ __half g_vt[(size_t)BSZ * DIM * SEQ];   // v proj, transposed [b][dim][s]
__device__ __half g_hctx[(size_t)MROWS * DIM];     // attention output
__device__ uint32_t g_mb[(size_t)SEQ * (SEQ / 32)]; // mask bit-packed, 64 w/row

// 0.125 (1/sqrt(64)) * log2(e): folded into Wq/bq so softmax can use exp2.
#define QSCALE 0.1803368801111137f

__device__ __forceinline__ uint32_t smem_u32(const void* p) {
    uint32_t a;
    asm("{ .reg .u64 t; cvta.to.shared.u64 t, %1; cvt.u32.u64 %0, t; }"
        : "=r"(a) : "l"(p));
    return a;
}

__device__ __forceinline__ void cp_async16(uint32_t dst, const void* src) {
    asm volatile("cp.async.cg.shared.global [%0], [%1], 16;"
                 :: "r"(dst), "l"(src));
}
#define CP_COMMIT() asm volatile("cp.async.commit_group;" ::: "memory")
#define CP_WAIT0()  asm volatile("cp.async.wait_group 0;" ::: "memory")
#define CP_WAIT1()  asm volatile("cp.async.wait_group 1;" ::: "memory")

__device__ __forceinline__ uint32_t pack_h2(float lo, float hi) {
    __half2 h = __floats2half2_rn(lo, hi);
    return *(uint32_t*)&h;
}

__device__ __forceinline__ float ex2(float x) {
    float r;
    asm("ex2.approx.ftz.f32 %0, %1;" : "=f"(r) : "f"(x));
    return r;
}

// ldmatrix x4: loads four 8x8 b16 tiles.
__device__ __forceinline__ void ldsm_x4(uint32_t& r0, uint32_t& r1,
                                        uint32_t& r2, uint32_t& r3,
                                        uint32_t addr) {
    asm volatile("ldmatrix.sync.aligned.m8n8.x4.shared.b16 "
                 "{%0,%1,%2,%3}, [%4];"
                 : "=r"(r0), "=r"(r1), "=r"(r2), "=r"(r3) : "r"(addr));
}

// m16n8k16 fp16 HMMA, fp32 accumulate.
__device__ __forceinline__ void mma_f16(float c[4],
                                        uint32_t a0, uint32_t a1,
                                        uint32_t a2, uint32_t a3,
                                        uint32_t b0, uint32_t b1) {
    asm volatile(
        "mma.sync.aligned.m16n8k16.row.col.f32.f16.f16.f32 "
        "{%0,%1,%2,%3}, {%4,%5,%6,%7}, {%8,%9}, {%0,%1,%2,%3};"
        : "+f"(c[0]), "+f"(c[1]), "+f"(c[2]), "+f"(c[3])
        : "r"(a0), "r"(a1), "r"(a2), "r"(a3), "r"(b0), "r"(b1));
}

// ---------------------------------------------------------------------------
// Fused prologue (one launch, branch on blockIdx.z):
//   z=0..2 : convert inputs Q/K/V fp32 -> fp16         (grid.x = 2048)
//   z=3    : pack mask to bits                          (grid.x = 512 used)
//   z=4..7 : weight transpose+convert (z-4 selects W)   (grid.x = 1024 used)
// ---------------------------------------------------------------------------
__global__ __launch_bounds__(256) void prologue_kernel(
    const float* __restrict__ Q, const float* __restrict__ K,
    const float* __restrict__ V, const int* __restrict__ mask,
    const float* __restrict__ Wq, const float* __restrict__ Wk,
    const float* __restrict__ Wv, const float* __restrict__ Wo)
{
    const int z = blockIdx.z;
    if (z < 3) {
        const float* src = (z == 0) ? Q : (z == 1) ? K : V;
        size_t off = ((size_t)blockIdx.x * 256 + threadIdx.x) * 8;
        float4 v0 = *(const float4*)(src + off);
        float4 v1 = *(const float4*)(src + off + 4);
        __half2* dst = (__half2*)(g_hin + (size_t)z * MROWS * DIM + off);
        uint4 pk;
        pk.x = pack_h2(v0.x, v0.y);
        pk.y = pack_h2(v0.z, v0.w);
        pk.z = pack_h2(v1.x, v1.y);
        pk.w = pack_h2(v1.z, v1.w);
        *(uint4*)dst = pk;
    } else if (z == 3) {
        if (blockIdx.x >= SEQ * (SEQ / 32) / 256) return;
        int idx = blockIdx.x * 256 + threadIdx.x;
        const int* src = mask + (size_t)idx * 32;
        uint32_t bits = 0;
#pragma unroll
        for (int u = 0; u < 8; ++u) {
            int4 v = *(const int4*)(src + u * 4);
            bits |= (v.x ? 1u : 0u) << (u * 4);
            bits |= (v.y ? 1u : 0u) << (u * 4 + 1);
            bits |= (v.z ? 1u : 0u) << (u * 4 + 2);
            bits |= (v.w ? 1u : 0u) << (u * 4 + 3);
        }
        g_mb[idx] = bits;
    } else {
        __shared__ float t[32][33];
        const int wz = z - 4;
        if (blockIdx.x >= 32 * 32) return;
        const float* W = (wz == 0) ? Wq : (wz == 1) ? Wk : (wz == 2) ? Wv : Wo;
        const float scale = (wz == 0) ? QSCALE : 1.0f;
        __half* WT = g_hwt + (size_t)wz * DIM * DIM;
        const int bx = (blockIdx.x & 31) * 32;   // n
        const int by = (blockIdx.x >> 5) * 32;   // k
        const int x = threadIdx.x & 31, y = threadIdx.x >> 5;
#pragma unroll
        for (int j = 0; j < 32; j += 8)
            t[y + j][x] = W[(size_t)(by + y + j) * DIM + bx + x];
        __syncthreads();
#pragma unroll
        for (int j = 0; j < 32; j += 8)
            WT[(size_t)(bx + y + j) * DIM + by + x] =
                __float2half(t[x][y + j] * scale);
    }
}

// ---------------------------------------------------------------------------
// fp16 GEMM (proven R12 pipeline): 128x128 tile, BK=64 (4 k16 steps/chunk),
// cp.async 3-stage, WAIT -> barrier -> prefetch, ldmatrix fragment loads.
// MODE 0: half row-major out.  MODE 1: half transposed out ([b][dim][s]).
// MODE 2: float row-major out.
// ---------------------------------------------------------------------------
#define GPAH 72                              // halves pitch => 144 B
#define SB_OFF (128 * GPAH * 2)              // 18432 B: B within stage
#define STAGE_BYTES (2 * 128 * GPAH * 2)     // 36864 B
#define OFF_BIAS_B (3 * STAGE_BYTES)         // 110592
#define GEMM_SMEM_BYTES (OFF_BIAS_B + 128 * 4)   // 111104

__device__ __forceinline__ void gemm_issue_h(
    uint32_t sbase, int s, int ch, const __half* __restrict__ A,
    const __half* __restrict__ WT, int m0, int n0, int tid)
{
    uint32_t sa = sbase + (uint32_t)(s * STAGE_BYTES);
    uint32_t sb = sa + SB_OFF;
    const __half* Ap = A + (size_t)m0 * DIM + ch * 64;
    const __half* Wp = WT + (size_t)n0 * DIM + ch * 64;
#pragma unroll
    for (int u = 0; u < 4; ++u) {
        int i = tid + u * 256;               // 1024: 128 rows x 8 chunks
        int row = i >> 3, c16 = i & 7;
        cp_async16(sa + (uint32_t)(row * 144 + c16 * 16),
                   Ap + (size_t)row * DIM + c16 * 8);
        cp_async16(sb + (uint32_t)(row * 144 + c16 * 16),
                   Wp + (size_t)row * DIM + c16 * 8);
    }
}

template <int MODE>
__device__ __forceinline__ void gemm_body_h(
    const __half* __restrict__ A, const __half* __restrict__ WT,
    const float* __restrict__ bias, void* Cout, float bscale, char* smc)
{
    float* sbias = (float*)(smc + OFF_BIAS_B);
    const uint32_t sbase = smem_u32(smc);
    const int tid = threadIdx.x;
    const int wid = tid >> 5, lane = tid & 31;
    const int wm = wid >> 2, wn = wid & 3;
    const int g = lane >> 2, tig = lane & 3;
    const int n0 = blockIdx.x * 128;
    const int m0 = blockIdx.y * 128;

    if (tid < 128) sbias[tid] = bias[n0 + tid] * bscale;

    const uint32_t afoff = (uint32_t)(
        (wm * 64 + ((lane >> 3) & 1) * 8 + (lane & 7)) * 144 +
        ((lane >> 4) & 1) * 16);
    const uint32_t bfoff = (uint32_t)(
        (wn * 32 + ((lane >> 4) & 1) * 8 + (lane & 7)) * 144 +
        ((lane >> 3) & 1) * 16);

    float c[4][4][4];
#pragma unroll
    for (int mt = 0; mt < 4; ++mt)
#pragma unroll
        for (int nt = 0; nt < 4; ++nt)
#pragma unroll
            for (int q = 0; q < 4; ++q) c[mt][nt][q] = 0.f;

    gemm_issue_h(sbase, 0, 0, A, WT, m0, n0, tid);
    CP_COMMIT();
    gemm_issue_h(sbase, 1, 1, A, WT, m0, n0, tid);
    CP_COMMIT();

    for (int ch = 0; ch < 16; ++ch) {
        if (ch == 15) CP_WAIT0(); else CP_WAIT1();
        __syncthreads();
        if (ch < 14) {
            gemm_issue_h(sbase, (ch + 2) % 3, ch + 2, A, WT, m0, n0, tid);
            CP_COMMIT();
        }

        const uint32_t sAb = sbase + (uint32_t)((ch % 3) * STAGE_BYTES);
        const uint32_t sBb = sAb + SB_OFF;

#pragma unroll
        for (int kk = 0; kk < 4; ++kk) {
            uint32_t af[4][4], bf[4][2];
#pragma unroll
            for (int mt = 0; mt < 4; ++mt)
                ldsm_x4(af[mt][0], af[mt][1], af[mt][2], af[mt][3],
                        sAb + afoff + mt * 2304 + kk * 32);
#pragma unroll
            for (int p = 0; p < 2; ++p)
                ldsm_x4(bf[2 * p][0], bf[2 * p][1],
                        bf[2 * p + 1][0], bf[2 * p + 1][1],
                        sBb + bfoff + p * 2304 + kk * 32);
#pragma unroll
            for (int mt = 0; mt < 4; ++mt)
#pragma unroll
                for (int nt = 0; nt < 4; ++nt)
                    mma_f16(c[mt][nt], af[mt][0], af[mt][1], af[mt][2],
                            af[mt][3], bf[nt][0], bf[nt][1]);
        }
    }

#pragma unroll
    for (int mt = 0; mt < 4; ++mt) {
        int row = m0 + wm * 64 + mt * 16 + g;
#pragma unroll
        for (int nt = 0; nt < 4; ++nt) {
            int col = n0 + wn * 32 + nt * 8 + 2 * tig;
            float b0 = sbias[col - n0], b1 = sbias[col - n0 + 1];
            float v00 = c[mt][nt][0] + b0, v01 = c[mt][nt][1] + b1;
            float v10 = c[mt][nt][2] + b0, v11 = c[mt][nt][3] + b1;
            if (MODE == 0) {
                __half* C = (__half*)Cout;
                *(uint32_t*)(C + (size_t)row * DIM + col) = pack_h2(v00, v01);
                *(uint32_t*)(C + (size_t)(row + 8) * DIM + col) =
                    pack_h2(v10, v11);
            } else if (MODE == 1) {
                __half* VT = (__half*)Cout;   // [b][dim][s]
                int bb = row >> 11, ss = row & 2047;
                VT[((size_t)bb * DIM + col) * SEQ + ss] = __float2half(v00);
                VT[((size_t)bb * DIM + col + 1) * SEQ + ss] = __float2half(v01);
                VT[((size_t)bb * DIM + col) * SEQ + ss + 8] = __float2half(v10);
                VT[((size_t)bb * DIM + col + 1) * SEQ + ss + 8] =
                    __float2half(v11);
            } else {
                float* C = (float*)Cout;
                *(float2*)(C + (size_t)row * DIM + col) = make_float2(v00, v01);
                *(float2*)(C + (size_t)(row + 8) * DIM + col) =
                    make_float2(v10, v11);
            }
        }
    }
}

__global__ __launch_bounds__(256, 2) void qkv_gemm_kernel(
    const float* __restrict__ bq, const float* __restrict__ bk,
    const float* __restrict__ bv)
{
    extern __shared__ char smc[];
    const int z = blockIdx.z;
    const __half* A = g_hin + (size_t)z * MROWS * DIM;
    const __half* WT = g_hwt + (size_t)z * DIM * DIM;
    if (z == 0)
        gemm_body_h<0>(A, WT, bq, g_hq, QSCALE, smc);
    else if (z == 1)
        gemm_body_h<0>(A, WT, bk, g_hk, 1.0f, smc);
    else
        gemm_body_h<1>(A, WT, bv, g_vt, 1.0f, smc);
}

__global__ __launch_bounds__(256, 2) void oproj_gemm_kernel(
    const float* __restrict__ bias, float* __restrict__ C)
{
    extern __shared__ char smc[];
    gemm_body_h<2>(g_hctx, g_hwt + (size_t)3 * DIM * DIM, bias, C, 1.0f, smc);
}

// ---------------------------------------------------------------------------
// FA2 attention: fp16 MMAs + ldmatrix + bit-packed mask.
// 128-key KV staging (one sync/wait/prefetch per 128 keys), processed in two
// 64-key halves with the R14 register working set.
// K stage: 128 rows x 144 B. V stage: 64 dim-rows x 272 B (128 keys).
// Block = 256 threads (8 warps) x 128 q rows; warp owns 16 q rows.
// ---------------------------------------------------------------------------
#define Q_BYTES (128 * 144)                   // 18432
#define KV_V_OFF (128 * 144)                  // 18432 (K part size)
#define KV_STAGE_B (128 * 144 + 64 * 272)     // 35840
#define ATTN_SMEM_BYTES (Q_BYTES + 2 * KV_STAGE_B)   // 90112

__global__ __launch_bounds__(256, 2) void attn_mma_kernel()
{
    extern __shared__ char smc[];
    const uint32_t sbase = smem_u32(smc);

    const int tid = threadIdx.x;
    const int wid = tid >> 5, lane = tid & 31;
    const int g = lane >> 2, tig = lane & 3;
    const int q0 = blockIdx.x * 128;
    const int h = blockIdx.y;
    const int b = blockIdx.z;

    const __half* qb = g_hq + ((size_t)b * SEQ + q0) * DIM + h * HDIM;
    const __half* kb = g_hk + (size_t)b * SEQ * DIM + h * HDIM;
    const __half* vtb = g_vt + ((size_t)b * DIM + h * HDIM) * SEQ;

    // ldmatrix per-lane address offsets.
    const uint32_t qoff = (uint32_t)(
        (wid * 16 + ((lane >> 3) & 1) * 8 + (lane & 7)) * 144 +
        ((lane >> 4) & 1) * 16);
    const uint32_t kfoff = (uint32_t)(
        (((lane >> 4) & 1) * 8 + (lane & 7)) * 144 +
        ((lane >> 3) & 1) * 16);
    const uint32_t vfoff = (uint32_t)(
        (((lane >> 4) & 1) * 8 + (lane & 7)) * 272 +
        ((lane >> 3) & 1) * 16);

    // Stage one 128-key KV tile (K: 128x144B, V: 64x272B).
    auto stage_kv = [&](int s, int kg) {
        uint32_t kst = sbase + Q_BYTES + (uint32_t)(s * KV_STAGE_B);
        uint32_t vst = kst + KV_V_OFF;
#pragma unroll
        for (int u = 0; u < 4; ++u) {
            int i = tid + u * 256;           // 1024
            int krow = i >> 3, kc = i & 7;   // K: 128 rows x 8 chunks
            cp_async16(kst + (uint32_t)(krow * 144 + kc * 16),
                       kb + (size_t)(kg + krow) * DIM + kc * 8);
            int vrow = i >> 4, vc = i & 15;  // V: 64 rows x 16 chunks
            cp_async16(vst + (uint32_t)(vrow * 272 + vc * 16),
                       vtb + (size_t)vrow * SEQ + kg + vc * 8);
        }
    };

    // Prologue: stage Q (128x64) + KV tile 0.
#pragma unroll
    for (int u = 0; u < 4; ++u) {
        int i = tid + u * 256;
        int row = i >> 3, c16 = i & 7;
        cp_async16(sbase + (uint32_t)(row * 144 + c16 * 16),
                   qb + (size_t)row * DIM + c16 * 8);
    }
    stage_kv(0, 0);
    CP_COMMIT();

    const int r0 = wid * 16 + g;
    float m0 = -1e30f, m1 = -1e30f, l0 = 0.f, l1 = 0.f;
    float o[8][4];
#pragma unroll
    for (int nt = 0; nt < 8; ++nt)
#pragma unroll
        for (int q = 0; q < 4; ++q) o[nt][q] = 0.f;

    // Bit-packed mask rows (64 words/row); uint4 covers 128 keys.
    const uint32_t* bmr0 = g_mb + (size_t)(q0 + r0) * (SEQ / 32);
    const uint32_t* bmr1 = bmr0 + 8 * (SEQ / 32);

    for (int kt = 0; kt < SEQ / 128; ++kt) {
        const int kg0 = kt * 128;

        uint4 w0 = *(const uint4*)(bmr0 + (kg0 >> 5));
        uint4 w1 = *(const uint4*)(bmr1 + (kg0 >> 5));

        CP_WAIT0();
        __syncthreads();

        if (kt < SEQ / 128 - 1) {
            stage_kv((kt + 1) & 1, (kt + 1) * 128);
            CP_COMMIT();
        }

        const uint32_t kbase_s = sbase + Q_BYTES
                                 + (uint32_t)((kt & 1) * KV_STAGE_B);
        const uint32_t vbase_s = kbase_s + KV_V_OFF;

#pragma unroll
        for (int hh = 0; hh < 2; ++hh) {
            const uint32_t khalf = kbase_s + (uint32_t)(hh * 64 * 144);
            const uint32_t vhalf = vbase_s + (uint32_t)(hh * 128);
            const uint32_t wa0 = hh ? w0.z : w0.x;
            const uint32_t wa1 = hh ? w0.w : w0.y;
            const uint32_t wb0 = hh ? w1.z : w1.x;
            const uint32_t wb1 = hh ? w1.w : w1.y;

            // S = Q @ K^T : 4 k16 steps, 8 n-tiles, S in registers.
            float c[8][4];
#pragma unroll
            for (int nt = 0; nt < 8; ++nt)
#pragma unroll
                for (int q = 0; q < 4; ++q) c[nt][q] = 0.f;

#pragma unroll
            for (int kk = 0; kk < 4; ++kk) {
                uint32_t a0, a1, a2, a3;
                ldsm_x4(a0, a1, a2, a3, sbase + qoff + kk * 32);
#pragma unroll
                for (int p = 0; p < 4; ++p) {
                    uint32_t b0, b1, b2, b3;
                    ldsm_x4(b0, b1, b2, b3,
                            khalf + kfoff + p * 2304 + kk * 32);
                    mma_f16(c[2 * p], a0, a1, a2, a3, b0, b1);
                    mma_f16(c[2 * p + 1], a0, a1, a2, a3, b2, b3);
                }
            }

            // Mask (bit tests) + row max (scores in log2 units).
            float mx0 = -1e30f, mx1 = -1e30f;
#pragma unroll
            for (int nt = 0; nt < 8; ++nt) {
                uint32_t wa = (nt < 4) ? wa0 : wa1;
                uint32_t wb = (nt < 4) ? wb0 : wb1;
                int sh = (nt & 3) * 8 + 2 * tig;
                uint32_t ta = wa >> sh, tb = wb >> sh;
                c[nt][0] = (ta & 1u) ? c[nt][0] : -1e30f;
                c[nt][1] = (ta & 2u) ? c[nt][1] : -1e30f;
                c[nt][2] = (tb & 1u) ? c[nt][2] : -1e30f;
                c[nt][3] = (tb & 2u) ? c[nt][3] : -1e30f;
                mx0 = fmaxf(mx0, fmaxf(c[nt][0], c[nt][1]));
                mx1 = fmaxf(mx1, fmaxf(c[nt][2], c[nt][3]));
            }
            mx0 = fmaxf(mx0, __shfl_xor_sync(0xffffffffu, mx0, 1));
            mx0 = fmaxf(mx0, __shfl_xor_sync(0xffffffffu, mx0, 2));
            mx1 = fmaxf(mx1, __shfl_xor_sync(0xffffffffu, mx1, 1));
            mx1 = fmaxf(mx1, __shfl_xor_sync(0xffffffffu, mx1, 2));

            float mn0 = fmaxf(m0, mx0), mn1 = fmaxf(m1, mx1);
            float al0 = ex2(m0 - mn0), al1 = ex2(m1 - mn1);
            float s0 = 0.f, s1 = 0.f;
#pragma unroll
            for (int nt = 0; nt < 8; ++nt) {
                float p0 = ex2(c[nt][0] - mn0);
                float p1 = ex2(c[nt][1] - mn0);
                float p2 = ex2(c[nt][2] - mn1);
                float p3 = ex2(c[nt][3] - mn1);
                s0 += p0 + p1;
                s1 += p2 + p3;
                c[nt][0] = p0; c[nt][1] = p1; c[nt][2] = p2; c[nt][3] = p3;
            }
            s0 += __shfl_xor_sync(0xffffffffu, s0, 1);
            s0 += __shfl_xor_sync(0xffffffffu, s0, 2);
            s1 += __shfl_xor_sync(0xffffffffu, s1, 1);
            s1 += __shfl_xor_sync(0xffffffffu, s1, 2);
            l0 = l0 * al0 + s0;
            l1 = l1 * al1 + s1;
            m0 = mn0; m1 = mn1;

#pragma unroll
            for (int nt = 0; nt < 8; ++nt) {
                o[nt][0] *= al0; o[nt][1] *= al0;
                o[nt][2] *= al1; o[nt][3] *= al1;
            }

            // O += P @ V: A-frags straight from the S C-frags (k16).
            // V n-tile stride: 16 dim-rows * 272 B = 4352 B per p.
#pragma unroll
            for (int kk = 0; kk < 4; ++kk) {
                uint32_t a0 = pack_h2(c[2 * kk][0], c[2 * kk][1]);
                uint32_t a1 = pack_h2(c[2 * kk][2], c[2 * kk][3]);
                uint32_t a2 = pack_h2(c[2 * kk + 1][0], c[2 * kk + 1][1]);
                uint32_t a3 = pack_h2(c[2 * kk + 1][2], c[2 * kk + 1][3]);
#pragma unroll
                for (int p = 0; p < 4; ++p) {
                    uint32_t b0, b1, b2, b3;
                    ldsm_x4(b0, b1, b2, b3,
                            vhalf + vfoff + p * 4352 + kk * 32);
                    mma_f16(o[2 * p], a0, a1, a2, a3, b0, b1);
                    mma_f16(o[2 * p + 1], a0, a1, a2, a3, b2, b3);
                }
            }
        }
    }

    // Final normalize + store fp16 (merged-head layout).
    float inv0 = 1.f / l0, inv1 = 1.f / l1;
    __half* od = g_hctx + ((size_t)b * SEQ + q0 + r0) * DIM + h * HDIM;
#pragma unroll
    for (int nt = 0; nt < 8; ++nt) {
        *(uint32_t*)(od + nt * 8 + 2 * tig) =
            pack_h2(o[nt][0] * inv0, o[nt][1] * inv0);
        *(uint32_t*)(od + (size_t)8 * DIM + nt * 8 + 2 * tig) =
            pack_h2(o[nt][2] * inv1, o[nt][3] * inv1);
    }
}

// ---------------------------------------------------------------------------
// Launch
// ---------------------------------------------------------------------------
extern "C" void kernel_launch(void* const* d_in, const int* in_sizes, int n_in,
                              void* d_out, int out_size)
{
    (void)in_sizes; (void)n_in; (void)out_size;
    const float* Q  = (const float*)d_in[0];
    const float* K  = (const float*)d_in[1];
    const float* V  = (const float*)d_in[2];
    const int* mask = (const int*)d_in[3];
    const float* Wq = (const float*)d_in[4];
    const float* bq = (const float*)d_in[5];
    const float* Wk = (const float*)d_in[6];
    const float* bk = (const float*)d_in[7];
    const float* Wv = (const float*)d_in[8];
    const float* bv = (const float*)d_in[9];
    const float* Wo = (const float*)d_in[10];
    const float* bo = (const float*)d_in[11];
    float* out = (float*)d_out;

    cudaFuncSetAttribute(qkv_gemm_kernel,
                         cudaFuncAttributeMaxDynamicSharedMemorySize,
                         GEMM_SMEM_BYTES);
    cudaFuncSetAttribute(oproj_gemm_kernel,
                         cudaFuncAttributeMaxDynamicSharedMemorySize,
                         GEMM_SMEM_BYTES);
    cudaFuncSetAttribute(attn_mma_kernel,
                         cudaFuncAttributeMaxDynamicSharedMemorySize,
                         ATTN_SMEM_BYTES);

    // Fused prologue: input converts (z=0..2), mask pack (z=3), W^T (z=4..7).
    dim3 pgrid(MROWS * DIM / (256 * 8), 1, 8);
    prologue_kernel<<<pgrid, 256>>>(Q, K, V, mask, Wq, Wk, Wv, Wo);

    // Batched QKV projections.
    dim3 qkvgrid(DIM / 128, MROWS / 128, 3);
    qkv_gemm_kernel<<<qkvgrid, 256, GEMM_SMEM_BYTES>>>(bq, bk, bv);

    // Attention.
    dim3 agrid(SEQ / 128, NHEAD, BSZ);  // (16, 16, 2)
    attn_mma_kernel<<<agrid, 256, ATTN_SMEM_BYTES>>>();

    // Output projection.
    dim3 ggrid(DIM / 128, MROWS / 128);
    oproj_gemm_kernel<<<ggrid, 256, GEMM_SMEM_BYTES>>>(bo, out);
}

// round 17
// speedup vs baseline: 1.1535x; 1.0155x over previous
#include <cuda_runtime.h>
#include <cuda_fp16.h>
#include <cstdint>

#define BSZ 2
#define SEQ 2048
#define DIM 1024
#define NHEAD 16
#define HDIM 64
#define MROWS (BSZ * SEQ)   // 4096

// Scratch (allocation-free requirement -> __device__ globals), all fp16.
__device__ __half g_hin[(size_t)3 * MROWS * DIM];  // converted inputs Q,K,V
__device__ __half g_hwt[(size_t)4 * DIM * DIM];    // W^T fp16 (Wq pre-scaled)
__device__ __half g_hq[(size_t)MROWS * DIM];       // q proj (scaled)
__device__ __half g_hk[(size_t)MROWS * DIM];       // k proj
__device__ __half g_vt[(size_t)BSZ * DIM * SEQ];   // v proj, transposed [b][dim][s]
__device__ __half g_hctx[(size_t)MROWS * DIM];     // attention output
__device__ uint32_t g_mb[(size_t)SEQ * (SEQ / 32)]; // mask bit-packed, 64 w/row

// 0.125 (1/sqrt(64)) * log2(e): folded into Wq/bq so softmax can use exp2.
#define QSCALE 0.1803368801111137f

__device__ __forceinline__ uint32_t smem_u32(const void* p) {
    uint32_t a;
    asm("{ .reg .u64 t; cvta.to.shared.u64 t, %1; cvt.u32.u64 %0, t; }"
        : "=r"(a) : "l"(p));
    return a;
}

__device__ __forceinline__ void cp_async16(uint32_t dst, const void* src) {
    asm volatile("cp.async.cg.shared.global [%0], [%1], 16;"
                 :: "r"(dst), "l"(src));
}
#define CP_COMMIT() asm volatile("cp.async.commit_group;" ::: "memory")
#define CP_WAIT0()  asm volatile("cp.async.wait_group 0;" ::: "memory")
#define CP_WAIT1()  asm volatile("cp.async.wait_group 1;" ::: "memory")

__device__ __forceinline__ uint32_t pack_h2(float lo, float hi) {
    __half2 h = __floats2half2_rn(lo, hi);
    return *(uint32_t*)&h;
}

__device__ __forceinline__ float ex2(float x) {
    float r;
    asm("ex2.approx.ftz.f32 %0, %1;" : "=f"(r) : "f"(x));
    return r;
}

__device__ __forceinline__ uint32_t ex2_h2(uint32_t x) {
    uint32_t r;
    asm("ex2.approx.f16x2 %0, %1;" : "=r"(r) : "r"(x));
    return r;
}

// ldmatrix x4: loads four 8x8 b16 tiles.
__device__ __forceinline__ void ldsm_x4(uint32_t& r0, uint32_t& r1,
                                        uint32_t& r2, uint32_t& r3,
                                        uint32_t addr) {
    asm volatile("ldmatrix.sync.aligned.m8n8.x4.shared.b16 "
                 "{%0,%1,%2,%3}, [%4];"
                 : "=r"(r0), "=r"(r1), "=r"(r2), "=r"(r3) : "r"(addr));
}

// m16n8k16 fp16 HMMA, fp32 accumulate.
__device__ __forceinline__ void mma_f16(float c[4],
                                        uint32_t a0, uint32_t a1,
                                        uint32_t a2, uint32_t a3,
                                        uint32_t b0, uint32_t b1) {
    asm volatile(
        "mma.sync.aligned.m16n8k16.row.col.f32.f16.f16.f32 "
        "{%0,%1,%2,%3}, {%4,%5,%6,%7}, {%8,%9}, {%0,%1,%2,%3};"
        : "+f"(c[0]), "+f"(c[1]), "+f"(c[2]), "+f"(c[3])
        : "r"(a0), "r"(a1), "r"(a2), "r"(a3), "r"(b0), "r"(b1));
}

// ---------------------------------------------------------------------------
// Fused prologue (one launch, branch on blockIdx.z):
//   z=0..2 : convert inputs Q/K/V fp32 -> fp16         (grid.x = 2048)
//   z=3    : pack mask to bits                          (grid.x = 512 used)
//   z=4..7 : weight transpose+convert (z-4 selects W)   (grid.x = 1024 used)
// ---------------------------------------------------------------------------
__global__ __launch_bounds__(256) void prologue_kernel(
    const float* __restrict__ Q, const float* __restrict__ K,
    const float* __restrict__ V, const int* __restrict__ mask,
    const float* __restrict__ Wq, const float* __restrict__ Wk,
    const float* __restrict__ Wv, const float* __restrict__ Wo)
{
    const int z = blockIdx.z;
    if (z < 3) {
        const float* src = (z == 0) ? Q : (z == 1) ? K : V;
        size_t off = ((size_t)blockIdx.x * 256 + threadIdx.x) * 8;
        float4 v0 = *(const float4*)(src + off);
        float4 v1 = *(const float4*)(src + off + 4);
        __half2* dst = (__half2*)(g_hin + (size_t)z * MROWS * DIM + off);
        uint4 pk;
        pk.x = pack_h2(v0.x, v0.y);
        pk.y = pack_h2(v0.z, v0.w);
        pk.z = pack_h2(v1.x, v1.y);
        pk.w = pack_h2(v1.z, v1.w);
        *(uint4*)dst = pk;
    } else if (z == 3) {
        if (blockIdx.x >= SEQ * (SEQ / 32) / 256) return;
        int idx = blockIdx.x * 256 + threadIdx.x;
        const int* src = mask + (size_t)idx * 32;
        uint32_t bits = 0;
#pragma unroll
        for (int u = 0; u < 8; ++u) {
            int4 v = *(const int4*)(src + u * 4);
            bits |= (v.x ? 1u : 0u) << (u * 4);
            bits |= (v.y ? 1u : 0u) << (u * 4 + 1);
            bits |= (v.z ? 1u : 0u) << (u * 4 + 2);
            bits |= (v.w ? 1u : 0u) << (u * 4 + 3);
        }
        g_mb[idx] = bits;
    } else {
        __shared__ float t[32][33];
        const int wz = z - 4;
        if (blockIdx.x >= 32 * 32) return;
        const float* W = (wz == 0) ? Wq : (wz == 1) ? Wk : (wz == 2) ? Wv : Wo;
        const float scale = (wz == 0) ? QSCALE : 1.0f;
        __half* WT = g_hwt + (size_t)wz * DIM * DIM;
        const int bx = (blockIdx.x & 31) * 32;   // n
        const int by = (blockIdx.x >> 5) * 32;   // k
        const int x = threadIdx.x & 31, y = threadIdx.x >> 5;
#pragma unroll
        for (int j = 0; j < 32; j += 8)
            t[y + j][x] = W[(size_t)(by + y + j) * DIM + bx + x];
        __syncthreads();
#pragma unroll
        for (int j = 0; j < 32; j += 8)
            WT[(size_t)(bx + y + j) * DIM + by + x] =
                __float2half(t[x][y + j] * scale);
    }
}

// ---------------------------------------------------------------------------
// fp16 GEMM (proven R12 pipeline): 128x128 tile, BK=64 (4 k16 steps/chunk),
// cp.async 3-stage, WAIT -> barrier -> prefetch, ldmatrix fragment loads.
// MODE 0: half row-major out.  MODE 1: half transposed out ([b][dim][s]).
// MODE 2: float row-major out.
// ---------------------------------------------------------------------------
#define GPAH 72                              // halves pitch => 144 B
#define SB_OFF (128 * GPAH * 2)              // 18432 B: B within stage
#define STAGE_BYTES (2 * 128 * GPAH * 2)     // 36864 B
#define OFF_BIAS_B (3 * STAGE_BYTES)         // 110592
#define GEMM_SMEM_BYTES (OFF_BIAS_B + 128 * 4)   // 111104

__device__ __forceinline__ void gemm_issue_h(
    uint32_t sbase, int s, int ch, const __half* __restrict__ A,
    const __half* __restrict__ WT, int m0, int n0, int tid)
{
    uint32_t sa = sbase + (uint32_t)(s * STAGE_BYTES);
    uint32_t sb = sa + SB_OFF;
    const __half* Ap = A + (size_t)m0 * DIM + ch * 64;
    const __half* Wp = WT + (size_t)n0 * DIM + ch * 64;
#pragma unroll
    for (int u = 0; u < 4; ++u) {
        int i = tid + u * 256;               // 1024: 128 rows x 8 chunks
        int row = i >> 3, c16 = i & 7;
        cp_async16(sa + (uint32_t)(row * 144 + c16 * 16),
                   Ap + (size_t)row * DIM + c16 * 8);
        cp_async16(sb + (uint32_t)(row * 144 + c16 * 16),
                   Wp + (size_t)row * DIM + c16 * 8);
    }
}

template <int MODE>
__device__ __forceinline__ void gemm_body_h(
    const __half* __restrict__ A, const __half* __restrict__ WT,
    const float* __restrict__ bias, void* Cout, float bscale, char* smc)
{
    float* sbias = (float*)(smc + OFF_BIAS_B);
    const uint32_t sbase = smem_u32(smc);
    const int tid = threadIdx.x;
    const int wid = tid >> 5, lane = tid & 31;
    const int wm = wid >> 2, wn = wid & 3;
    const int g = lane >> 2, tig = lane & 3;
    const int n0 = blockIdx.x * 128;
    const int m0 = blockIdx.y * 128;

    if (tid < 128) sbias[tid] = bias[n0 + tid] * bscale;

    const uint32_t afoff = (uint32_t)(
        (wm * 64 + ((lane >> 3) & 1) * 8 + (lane & 7)) * 144 +
        ((lane >> 4) & 1) * 16);
    const uint32_t bfoff = (uint32_t)(
        (wn * 32 + ((lane >> 4) & 1) * 8 + (lane & 7)) * 144 +
        ((lane >> 3) & 1) * 16);

    float c[4][4][4];
#pragma unroll
    for (int mt = 0; mt < 4; ++mt)
#pragma unroll
        for (int nt = 0; nt < 4; ++nt)
#pragma unroll
            for (int q = 0; q < 4; ++q) c[mt][nt][q] = 0.f;

    gemm_issue_h(sbase, 0, 0, A, WT, m0, n0, tid);
    CP_COMMIT();
    gemm_issue_h(sbase, 1, 1, A, WT, m0, n0, tid);
    CP_COMMIT();

    for (int ch = 0; ch < 16; ++ch) {
        if (ch == 15) CP_WAIT0(); else CP_WAIT1();
        __syncthreads();
        if (ch < 14) {
            gemm_issue_h(sbase, (ch + 2) % 3, ch + 2, A, WT, m0, n0, tid);
            CP_COMMIT();
        }

        const uint32_t sAb = sbase + (uint32_t)((ch % 3) * STAGE_BYTES);
        const uint32_t sBb = sAb + SB_OFF;

#pragma unroll
        for (int kk = 0; kk < 4; ++kk) {
            uint32_t af[4][4], bf[4][2];
#pragma unroll
            for (int mt = 0; mt < 4; ++mt)
                ldsm_x4(af[mt][0], af[mt][1], af[mt][2], af[mt][3],
                        sAb + afoff + mt * 2304 + kk * 32);
#pragma unroll
            for (int p = 0; p < 2; ++p)
                ldsm_x4(bf[2 * p][0], bf[2 * p][1],
                        bf[2 * p + 1][0], bf[2 * p + 1][1],
                        sBb + bfoff + p * 2304 + kk * 32);
#pragma unroll
            for (int mt = 0; mt < 4; ++mt)
#pragma unroll
                for (int nt = 0; nt < 4; ++nt)
                    mma_f16(c[mt][nt], af[mt][0], af[mt][1], af[mt][2],
                            af[mt][3], bf[nt][0], bf[nt][1]);
        }
    }

#pragma unroll
    for (int mt = 0; mt < 4; ++mt) {
        int row = m0 + wm * 64 + mt * 16 + g;
#pragma unroll
        for (int nt = 0; nt < 4; ++nt) {
            int col = n0 + wn * 32 + nt * 8 + 2 * tig;
            float b0 = sbias[col - n0], b1 = sbias[col - n0 + 1];
            float v00 = c[mt][nt][0] + b0, v01 = c[mt][nt][1] + b1;
            float v10 = c[mt][nt][2] + b0, v11 = c[mt][nt][3] + b1;
            if (MODE == 0) {
                __half* C = (__half*)Cout;
                *(uint32_t*)(C + (size_t)row * DIM + col) = pack_h2(v00, v01);
                *(uint32_t*)(C + (size_t)(row + 8) * DIM + col) =
                    pack_h2(v10, v11);
            } else if (MODE == 1) {
                __half* VT = (__half*)Cout;   // [b][dim][s]
                int bb = row >> 11, ss = row & 2047;
                VT[((size_t)bb * DIM + col) * SEQ + ss] = __float2half(v00);
                VT[((size_t)bb * DIM + col + 1) * SEQ + ss] = __float2half(v01);
                VT[((size_t)bb * DIM + col) * SEQ + ss + 8] = __float2half(v10);
                VT[((size_t)bb * DIM + col + 1) * SEQ + ss + 8] =
                    __float2half(v11);
            } else {
                float* C = (float*)Cout;
                *(float2*)(C + (size_t)row * DIM + col) = make_float2(v00, v01);
                *(float2*)(C + (size_t)(row + 8) * DIM + col) =
                    make_float2(v10, v11);
            }
        }
    }
}

__global__ __launch_bounds__(256, 2) void qkv_gemm_kernel(
    const float* __restrict__ bq, const float* __restrict__ bk,
    const float* __restrict__ bv)
{
    extern __shared__ char smc[];
    const int z = blockIdx.z;
    const __half* A = g_hin + (size_t)z * MROWS * DIM;
    const __half* WT = g_hwt + (size_t)z * DIM * DIM;
    if (z == 0)
        gemm_body_h<0>(A, WT, bq, g_hq, QSCALE, smc);
    else if (z == 1)
        gemm_body_h<0>(A, WT, bk, g_hk, 1.0f, smc);
    else
        gemm_body_h<1>(A, WT, bv, g_vt, 1.0f, smc);
}

__global__ __launch_bounds__(256, 2) void oproj_gemm_kernel(
    const float* __restrict__ bias, float* __restrict__ C)
{
    extern __shared__ char smc[];
    gemm_body_h<2>(g_hctx, g_hwt + (size_t)3 * DIM * DIM, bias, C, 1.0f, smc);
}

// ---------------------------------------------------------------------------
// FA2 attention: fp16 MMAs + ldmatrix + bit-packed mask.
// 128-key KV staging, two 64-key halves. Softmax: ex2.f16x2 (P lands directly
// in A-frag form) + row-sum l via all-ones-B MMA (no LDS, no shuffles).
// Block = 256 threads (8 warps) x 128 q rows; warp owns 16 q rows.
// ---------------------------------------------------------------------------
#define Q_BYTES (128 * 144)                   // 18432
#define KV_V_OFF (128 * 144)                  // 18432 (K part size)
#define KV_STAGE_B (128 * 144 + 64 * 272)     // 35840
#define ATTN_SMEM_BYTES (Q_BYTES + 2 * KV_STAGE_B)   // 90112
#define ONES_H2 0x3C003C00u

__global__ __launch_bounds__(256, 2) void attn_mma_kernel()
{
    extern __shared__ char smc[];
    const uint32_t sbase = smem_u32(smc);

    const int tid = threadIdx.x;
    const int wid = tid >> 5, lane = tid & 31;
    const int g = lane >> 2, tig = lane & 3;
    const int q0 = blockIdx.x * 128;
    const int h = blockIdx.y;
    const int b = blockIdx.z;

    const __half* qb = g_hq + ((size_t)b * SEQ + q0) * DIM + h * HDIM;
    const __half* kb = g_hk + (size_t)b * SEQ * DIM + h * HDIM;
    const __half* vtb = g_vt + ((size_t)b * DIM + h * HDIM) * SEQ;

    // ldmatrix per-lane address offsets.
    const uint32_t qoff = (uint32_t)(
        (wid * 16 + ((lane >> 3) & 1) * 8 + (lane & 7)) * 144 +
        ((lane >> 4) & 1) * 16);
    const uint32_t kfoff = (uint32_t)(
        (((lane >> 4) & 1) * 8 + (lane & 7)) * 144 +
        ((lane >> 3) & 1) * 16);
    const uint32_t vfoff = (uint32_t)(
        (((lane >> 4) & 1) * 8 + (lane & 7)) * 272 +
        ((lane >> 3) & 1) * 16);

    // Stage one 128-key KV tile (K: 128x144B, V: 64x272B).
    auto stage_kv = [&](int s, int kg) {
        uint32_t kst = sbase + Q_BYTES + (uint32_t)(s * KV_STAGE_B);
        uint32_t vst = kst + KV_V_OFF;
#pragma unroll
        for (int u = 0; u < 4; ++u) {
            int i = tid + u * 256;           // 1024
            int krow = i >> 3, kc = i & 7;   // K: 128 rows x 8 chunks
            cp_async16(kst + (uint32_t)(krow * 144 + kc * 16),
                       kb + (size_t)(kg + krow) * DIM + kc * 8);
            int vrow = i >> 4, vc = i & 15;  // V: 64 rows x 16 chunks
            cp_async16(vst + (uint32_t)(vrow * 272 + vc * 16),
                       vtb + (size_t)vrow * SEQ + kg + vc * 8);
        }
    };

    // Prologue: stage Q (128x64) + KV tile 0.
#pragma unroll
    for (int u = 0; u < 4; ++u) {
        int i = tid + u * 256;
        int row = i >> 3, c16 = i & 7;
        cp_async16(sbase + (uint32_t)(row * 144 + c16 * 16),
                   qb + (size_t)row * DIM + c16 * 8);
    }
    stage_kv(0, 0);
    CP_COMMIT();

    const int r0 = wid * 16 + g;
    float m0 = -1e30f, m1 = -1e30f, l0 = 0.f, l1 = 0.f;
    float o[8][4];
#pragma unroll
    for (int nt = 0; nt < 8; ++nt)
#pragma unroll
        for (int q = 0; q < 4; ++q) o[nt][q] = 0.f;

    // Bit-packed mask rows (64 words/row); uint4 covers 128 keys.
    const uint32_t* bmr0 = g_mb + (size_t)(q0 + r0) * (SEQ / 32);
    const uint32_t* bmr1 = bmr0 + 8 * (SEQ / 32);

    for (int kt = 0; kt < SEQ / 128; ++kt) {
        const int kg0 = kt * 128;

        uint4 w0 = *(const uint4*)(bmr0 + (kg0 >> 5));
        uint4 w1 = *(const uint4*)(bmr1 + (kg0 >> 5));

        CP_WAIT0();
        __syncthreads();

        if (kt < SEQ / 128 - 1) {
            stage_kv((kt + 1) & 1, (kt + 1) * 128);
            CP_COMMIT();
        }

        const uint32_t kbase_s = sbase + Q_BYTES
                                 + (uint32_t)((kt & 1) * KV_STAGE_B);
        const uint32_t vbase_s = kbase_s + KV_V_OFF;

#pragma unroll
        for (int hh = 0; hh < 2; ++hh) {
            const uint32_t khalf = kbase_s + (uint32_t)(hh * 64 * 144);
            const uint32_t vhalf = vbase_s + (uint32_t)(hh * 128);
            const uint32_t wa0 = hh ? w0.z : w0.x;
            const uint32_t wa1 = hh ? w0.w : w0.y;
            const uint32_t wb0 = hh ? w1.z : w1.x;
            const uint32_t wb1 = hh ? w1.w : w1.y;

            // S = Q @ K^T : 4 k16 steps, 8 n-tiles, S in registers.
            float c[8][4];
#pragma unroll
            for (int nt = 0; nt < 8; ++nt)
#pragma unroll
                for (int q = 0; q < 4; ++q) c[nt][q] = 0.f;

#pragma unroll
            for (int kk = 0; kk < 4; ++kk) {
                uint32_t a0, a1, a2, a3;
                ldsm_x4(a0, a1, a2, a3, sbase + qoff + kk * 32);
#pragma unroll
                for (int p = 0; p < 4; ++p) {
                    uint32_t b0, b1, b2, b3;
                    ldsm_x4(b0, b1, b2, b3,
                            khalf + kfoff + p * 2304 + kk * 32);
                    mma_f16(c[2 * p], a0, a1, a2, a3, b0, b1);
                    mma_f16(c[2 * p + 1], a0, a1, a2, a3, b2, b3);
                }
            }

            // Mask (bit tests) + row max (scores in log2 units).
            float mx0 = -1e30f, mx1 = -1e30f;
#pragma unroll
            for (int nt = 0; nt < 8; ++nt) {
                uint32_t wa = (nt < 4) ? wa0 : wa1;
                uint32_t wb = (nt < 4) ? wb0 : wb1;
                int sh = (nt & 3) * 8 + 2 * tig;
                uint32_t ta = wa >> sh, tb = wb >> sh;
                c[nt][0] = (ta & 1u) ? c[nt][0] : -1e30f;
                c[nt][1] = (ta & 2u) ? c[nt][1] : -1e30f;
                c[nt][2] = (tb & 1u) ? c[nt][2] : -1e30f;
                c[nt][3] = (tb & 2u) ? c[nt][3] : -1e30f;
                mx0 = fmaxf(mx0, fmaxf(c[nt][0], c[nt][1]));
                mx1 = fmaxf(mx1, fmaxf(c[nt][2], c[nt][3]));
            }
            mx0 = fmaxf(mx0, __shfl_xor_sync(0xffffffffu, mx0, 1));
            mx0 = fmaxf(mx0, __shfl_xor_sync(0xffffffffu, mx0, 2));
            mx1 = fmaxf(mx1, __shfl_xor_sync(0xffffffffu, mx1, 1));
            mx1 = fmaxf(mx1, __shfl_xor_sync(0xffffffffu, mx1, 2));

            float mn0 = fmaxf(m0, mx0), mn1 = fmaxf(m1, mx1);
            float al0 = ex2(m0 - mn0), al1 = ex2(m1 - mn1);

            // P = exp2(S - m) straight into fp16 A-fragments (ex2.f16x2);
            // masked lanes are -1e30 -> fp16 -inf -> exp 0.
            uint32_t pa[4][4];
#pragma unroll
            for (int kk = 0; kk < 4; ++kk) {
                pa[kk][0] = ex2_h2(pack_h2(c[2 * kk][0] - mn0,
                                           c[2 * kk][1] - mn0));
                pa[kk][1] = ex2_h2(pack_h2(c[2 * kk][2] - mn1,
                                           c[2 * kk][3] - mn1));
                pa[kk][2] = ex2_h2(pack_h2(c[2 * kk + 1][0] - mn0,
                                           c[2 * kk + 1][1] - mn0));
                pa[kk][3] = ex2_h2(pack_h2(c[2 * kk + 1][2] - mn1,
                                           c[2 * kk + 1][3] - mn1));
            }

            // Row sums via all-ones-B MMA: ls[0]=rowsum(g), ls[2]=rowsum(g+8).
            float ls[4] = {0.f, 0.f, 0.f, 0.f};
#pragma unroll
            for (int kk = 0; kk < 4; ++kk)
                mma_f16(ls, pa[kk][0], pa[kk][1], pa[kk][2], pa[kk][3],
                        ONES_H2, ONES_H2);

            l0 = l0 * al0 + ls[0];
            l1 = l1 * al1 + ls[2];
            m0 = mn0; m1 = mn1;

#pragma unroll
            for (int nt = 0; nt < 8; ++nt) {
                o[nt][0] *= al0; o[nt][1] *= al0;
                o[nt][2] *= al1; o[nt][3] *= al1;
            }

            // O += P @ V (V n-tile stride: 16 dim-rows * 272 B = 4352 B).
#pragma unroll
            for (int kk = 0; kk < 4; ++kk) {
#pragma unroll
                for (int p = 0; p < 4; ++p) {
                    uint32_t b0, b1, b2, b3;
                    ldsm_x4(b0, b1, b2, b3,
                            vhalf + vfoff + p * 4352 + kk * 32);
                    mma_f16(o[2 * p], pa[kk][0], pa[kk][1], pa[kk][2],
                            pa[kk][3], b0, b1);
                    mma_f16(o[2 * p + 1], pa[kk][0], pa[kk][1], pa[kk][2],
                            pa[kk][3], b2, b3);
                }
            }
        }
    }

    // Final normalize + store fp16 (merged-head layout).
    float inv0 = 1.f / l0, inv1 = 1.f / l1;
    __half* od = g_hctx + ((size_t)b * SEQ + q0 + r0) * DIM + h * HDIM;
#pragma unroll
    for (int nt = 0; nt < 8; ++nt) {
        *(uint32_t*)(od + nt * 8 + 2 * tig) =
            pack_h2(o[nt][0] * inv0, o[nt][1] * inv0);
        *(uint32_t*)(od + (size_t)8 * DIM + nt * 8 + 2 * tig) =
            pack_h2(o[nt][2] * inv1, o[nt][3] * inv1);
    }
}

// ---------------------------------------------------------------------------
// Launch
// ---------------------------------------------------------------------------
extern "C" void kernel_launch(void* const* d_in, const int* in_sizes, int n_in,
                              void* d_out, int out_size)
{
    (void)in_sizes; (void)n_in; (void)out_size;
    const float* Q  = (const float*)d_in[0];
    const float* K  = (const float*)d_in[1];
    const float* V  = (const float*)d_in[2];
    const int* mask = (const int*)d_in[3];
    const float* Wq = (const float*)d_in[4];
    const float* bq = (const float*)d_in[5];
    const float* Wk = (const float*)d_in[6];
    const float* bk = (const float*)d_in[7];
    const float* Wv = (const float*)d_in[8];
    const float* bv = (const float*)d_in[9];
    const float* Wo = (const float*)d_in[10];
    const float* bo = (const float*)d_in[11];
    float* out = (float*)d_out;

    cudaFuncSetAttribute(qkv_gemm_kernel,
                         cudaFuncAttributeMaxDynamicSharedMemorySize,
                         GEMM_SMEM_BYTES);
    cudaFuncSetAttribute(oproj_gemm_kernel,
                         cudaFuncAttributeMaxDynamicSharedMemorySize,
                         GEMM_SMEM_BYTES);
    cudaFuncSetAttribute(attn_mma_kernel,
                         cudaFuncAttributeMaxDynamicSharedMemorySize,
                         ATTN_SMEM_BYTES);

    // Fused prologue: input converts (z=0..2), mask pack (z=3), W^T (z=4..7).
    dim3 pgrid(MROWS * DIM / (256 * 8), 1, 8);
    prologue_kernel<<<pgrid, 256>>>(Q, K, V, mask, Wq, Wk, Wv, Wo);

    // Batched QKV projections.
    dim3 qkvgrid(DIM / 128, MROWS / 128, 3);
    qkv_gemm_kernel<<<qkvgrid, 256, GEMM_SMEM_BYTES>>>(bq, bk, bv);

    // Attention.
    dim3 agrid(SEQ / 128, NHEAD, BSZ);  // (16, 16, 2)
    attn_mma_kernel<<<agrid, 256, ATTN_SMEM_BYTES>>>();

    // Output projection.
    dim3 ggrid(DIM / 128, MROWS / 128);
    oproj_gemm_kernel<<<ggrid, 256, GEMM_SMEM_BYTES>>>(bo, out);
}